// round 1
// baseline (speedup 1.0000x reference)
#include <cuda_runtime.h>
#include <math.h>

#define Bc 4
#define Cc 512
#define Tc 8
#define Lc 512
#define Hc 8
#define HD 64
#define BT 32               // B*T
#define CTL (Cc*Tc*Lc)
#define TL  (Tc*Lc)

// ---------------- scratch (device globals; no allocation allowed) ----------
__device__ __align__(16) float g_ept  [(size_t)BT*Lc*Cc];     // e transposed  (bt,l,c)
__device__ __align__(16) float g_xpt  [(size_t)BT*Lc*Cc];     // x transposed  (bt,l,c)
__device__ __align__(16) float g_pooled[BT*Cc];
__device__ __align__(16) float g_gw   [BT*Hc];
__device__ __align__(16) float g_qraw [(size_t)BT*Lc*Cc];     // (bt,l,c)
__device__ __align__(16) float g_kvraw[(size_t)BT*Lc*2*Cc];   // (bt,l,2c)
__device__ __align__(16) float g_q    [(size_t)BT*Hc*Lc*HD];  // (bt,h,l,d)
__device__ __align__(16) float g_k    [(size_t)BT*Hc*Lc*HD];
__device__ __align__(16) float g_v    [(size_t)BT*Hc*Lc*HD];
__device__ __align__(16) float g_o    [(size_t)BT*Lc*Cc];     // attn out (bt,l,c)
__device__ __align__(16) float g_proj [(size_t)BT*Lc*Cc];     // out-proj (bt,l,c)

// ---------------- transpose (b,c,t,l) -> (bt,l,c) --------------------------
__global__ void k_transpose(const float* __restrict__ src, float* __restrict__ dst) {
    __shared__ float tile[32][33];
    int bt = blockIdx.z;
    int b = bt / Tc, t = bt % Tc;
    int l0 = blockIdx.x * 32;
    int c0 = blockIdx.y * 32;
    const float* s = src + (size_t)b*CTL + (size_t)t*Lc;   // + c*TL + l
    int tx = threadIdx.x, ty = threadIdx.y;
    #pragma unroll
    for (int j = 0; j < 32; j += 8)
        tile[ty+j][tx] = s[(size_t)(c0+ty+j)*TL + l0 + tx];
    __syncthreads();
    float* d = dst + (size_t)bt*Lc*Cc;
    #pragma unroll
    for (int j = 0; j < 32; j += 8)
        d[(size_t)(l0+ty+j)*Cc + c0 + tx] = tile[tx][ty+j];
}

// ---------------- pooled[bt,c] = mean_l e[b,c,t,l] --------------------------
__global__ void k_pool(const float* __restrict__ e) {
    int w    = (blockIdx.x * blockDim.x + threadIdx.x) >> 5;
    int lane = threadIdx.x & 31;
    if (w >= BT*Cc) return;
    int bt = w / Cc, c = w % Cc;
    int b = bt / Tc, t = bt % Tc;
    const float* p = e + (size_t)b*CTL + (size_t)c*TL + (size_t)t*Lc;
    float s = 0.f;
    #pragma unroll 4
    for (int l = lane; l < Lc; l += 32) s += p[l];
    #pragma unroll
    for (int o = 16; o; o >>= 1) s += __shfl_xor_sync(0xffffffffu, s, o);
    if (!lane) g_pooled[w] = s * (1.0f/Lc);
}

// ---------------- gating: gw = softmax(tanh(pooled@Wg1^T+bg1)@Wg2^T+bg2) ----
__global__ void k_gate(const float* __restrict__ Wg1, const float* __restrict__ bg1,
                       const float* __restrict__ Wg2, const float* __restrict__ bg2) {
    __shared__ float sp[Cc], sh1[Cc], sg[Hc];
    int bt = blockIdx.x;
    int tid = threadIdx.x;                       // 512 threads
    sp[tid] = g_pooled[bt*Cc + tid];
    __syncthreads();
    float acc = bg1[tid];
    const float* wr = Wg1 + (size_t)tid*Cc;
    #pragma unroll 8
    for (int k = 0; k < Cc; ++k) acc += sp[k]*wr[k];
    sh1[tid] = tanhf(acc);
    __syncthreads();
    int warp = tid >> 5, lane = tid & 31;
    if (warp < Hc) {
        const float* w2 = Wg2 + (size_t)warp*Cc;
        float a = 0.f;
        #pragma unroll 4
        for (int k = lane; k < Cc; k += 32) a += sh1[k]*w2[k];
        #pragma unroll
        for (int o = 16; o; o >>= 1) a += __shfl_xor_sync(0xffffffffu, a, o);
        if (!lane) sg[warp] = a + bg2[warp];
    }
    __syncthreads();
    if (tid == 0) {
        float mx = sg[0];
        #pragma unroll
        for (int h = 1; h < Hc; ++h) mx = fmaxf(mx, sg[h]);
        float ex[Hc], ssum = 0.f;
        #pragma unroll
        for (int h = 0; h < Hc; ++h) { ex[h] = expf(sg[h]-mx); ssum += ex[h]; }
        #pragma unroll
        for (int h = 0; h < Hc; ++h) g_gw[bt*Hc+h] = ex[h]/ssum;
    }
}

// ---------------- SGEMM: C[bt][m][n] = A[bt][m][:] . W[n][:] + bias[n] ------
// which: 0 = Q (A=g_ept, C=g_qraw, N=512)
//        1 = KV (A=g_xpt, C=g_kvraw, N=1024)
//        2 = proj (A=g_o, C=g_proj, N=512)
__global__ void __launch_bounds__(256) k_sgemm_nt(int which,
    const float* __restrict__ W, const float* __restrict__ bias) {
    const float* A; float* Cm; int N;
    if      (which == 0) { A = g_ept; Cm = g_qraw;  N = 512;  }
    else if (which == 1) { A = g_xpt; Cm = g_kvraw; N = 1024; }
    else                 { A = g_o;   Cm = g_proj;  N = 512;  }

    __shared__ float As[8][128];
    __shared__ float Ws[8][128];
    int bt = blockIdx.z;
    const float* Ab = A + (size_t)bt * (Lc*Cc);
    float* Cb = Cm + (size_t)bt * Lc * N;
    int m0 = blockIdx.y * 128;
    int n0 = blockIdx.x * 128;
    int tid  = threadIdx.x;
    int lrow = tid >> 1;
    int lk4  = (tid & 1) * 4;
    int tm0  = (tid >> 4) * 8;
    int tn0  = (tid & 15) * 8;
    float acc[8][8] = {};
    for (int k0 = 0; k0 < Cc; k0 += 8) {
        float4 av = *(const float4*)(Ab + (size_t)(m0+lrow)*Cc + k0 + lk4);
        float4 wv = *(const float4*)(W  + (size_t)(n0+lrow)*Cc + k0 + lk4);
        As[lk4+0][lrow]=av.x; As[lk4+1][lrow]=av.y; As[lk4+2][lrow]=av.z; As[lk4+3][lrow]=av.w;
        Ws[lk4+0][lrow]=wv.x; Ws[lk4+1][lrow]=wv.y; Ws[lk4+2][lrow]=wv.z; Ws[lk4+3][lrow]=wv.w;
        __syncthreads();
        #pragma unroll
        for (int kk = 0; kk < 8; ++kk) {
            float ra[8], rb[8];
            #pragma unroll
            for (int i = 0; i < 8; ++i) ra[i] = As[kk][tm0+i];
            #pragma unroll
            for (int j = 0; j < 8; ++j) rb[j] = Ws[kk][tn0+j];
            #pragma unroll
            for (int i = 0; i < 8; ++i)
                #pragma unroll
                for (int j = 0; j < 8; ++j) acc[i][j] += ra[i]*rb[j];
        }
        __syncthreads();
    }
    #pragma unroll
    for (int i = 0; i < 8; ++i) {
        float* crow = Cb + (size_t)(m0+tm0+i)*N + n0 + tn0;
        #pragma unroll
        for (int j = 0; j < 8; ++j) crow[j] = acc[i][j] + bias[n0+tn0+j];
    }
}

// ---------------- normalize Q rows (over hd=64) -----------------------------
__global__ void k_norm_q() {
    int w    = (blockIdx.x*blockDim.x + threadIdx.x) >> 5;   // one warp per (bt,l,h)
    int lane = threadIdx.x & 31;
    if (w >= BT*Lc*Hc) return;
    int h = w % Hc; int tmp = w / Hc; int l = tmp % Lc; int bt = tmp / Lc;
    const float* src = g_qraw + ((size_t)(bt*Lc + l))*Cc + h*HD;
    float v0 = src[lane], v1 = src[lane+32];
    float ss = v0*v0 + v1*v1;
    #pragma unroll
    for (int o = 16; o; o >>= 1) ss += __shfl_xor_sync(0xffffffffu, ss, o);
    float inv = 1.0f / fmaxf(sqrtf(ss), 1e-12f);
    float* dst = g_q + (((size_t)(bt*Hc + h))*Lc + l)*HD;
    dst[lane] = v0*inv; dst[lane+32] = v1*inv;
}

// ---------------- normalize K/V rows; V gets gw factor ----------------------
__global__ void k_norm_kv() {
    int w    = (blockIdx.x*blockDim.x + threadIdx.x) >> 5;   // warp per (bt,l,g)
    int lane = threadIdx.x & 31;
    if (w >= BT*Lc*16) return;
    int g = w % 16; int tmp = w / 16; int l = tmp % Lc; int bt = tmp / Lc;
    const float* src = g_kvraw + ((size_t)(bt*Lc + l))*(2*Cc) + g*HD;
    float v0 = src[lane], v1 = src[lane+32];
    float ss = v0*v0 + v1*v1;
    #pragma unroll
    for (int o = 16; o; o >>= 1) ss += __shfl_xor_sync(0xffffffffu, ss, o);
    float inv = 1.0f / fmaxf(sqrtf(ss), 1e-12f);
    if (g < Hc) {
        float* dst = g_k + (((size_t)(bt*Hc + g))*Lc + l)*HD;
        dst[lane] = v0*inv; dst[lane+32] = v1*inv;
    } else {
        int h = g - Hc;
        float s = inv * g_gw[bt*Hc + h];
        float* dst = g_v + (((size_t)(bt*Hc + h))*Lc + l)*HD;
        dst[lane] = v0*s; dst[lane+32] = v1*s;
    }
}

// ---------------- attention: per (bt,h), 64 q-rows / block, online softmax --
__global__ void __launch_bounds__(256) k_attn() {
    __shared__ float sq[64][65];
    __shared__ float sk[32][65];
    __shared__ float sv[32][65];
    __shared__ float sp[64][33];
    __shared__ float sm_[64], sl_[64], sal[64];
    int l0 = blockIdx.x * 64;
    int h  = blockIdx.y;
    int bt = blockIdx.z;
    int tid = threadIdx.x;
    const float* q  = g_q + ((size_t)(bt*Hc+h)*Lc)*HD;
    const float* kp = g_k + ((size_t)(bt*Hc+h)*Lc)*HD;
    const float* vp = g_v + ((size_t)(bt*Hc+h)*Lc)*HD;
    const float scale = 0.125f;                 // 1/sqrt(64)
    for (int i = tid; i < 64*64; i += 256) {
        int r = i >> 6, d = i & 63;
        sq[r][d] = q[(size_t)(l0+r)*HD + d] * scale;
    }
    if (tid < 64) { sm_[tid] = -1e30f; sl_[tid] = 0.f; }
    float acc[4][4] = {};
    int pr = (tid >> 4) * 4, pc = (tid & 15) * 4;   // PV mapping (64 x 64)
    int sr = (tid >> 4) * 4, sc = (tid & 15) * 2;   // S mapping  (64 x 32)
    __syncthreads();
    for (int jt = 0; jt < Lc; jt += 32) {
        for (int i = tid; i < 32*64; i += 256) {
            int r = i >> 6, d = i & 63;
            sk[r][d] = kp[(size_t)(jt+r)*HD + d];
            sv[r][d] = vp[(size_t)(jt+r)*HD + d];
        }
        __syncthreads();
        float s[4][2] = {};
        #pragma unroll
        for (int d = 0; d < 64; ++d) {
            float qr[4], kr[2];
            #pragma unroll
            for (int i = 0; i < 4; ++i) qr[i] = sq[sr+i][d];
            kr[0] = sk[sc][d]; kr[1] = sk[sc+1][d];
            #pragma unroll
            for (int i = 0; i < 4; ++i) { s[i][0] += qr[i]*kr[0]; s[i][1] += qr[i]*kr[1]; }
        }
        #pragma unroll
        for (int i = 0; i < 4; ++i) { sp[sr+i][sc] = s[i][0]; sp[sr+i][sc+1] = s[i][1]; }
        __syncthreads();
        if (tid < 64) {
            float mx = sm_[tid];
            #pragma unroll
            for (int j = 0; j < 32; ++j) mx = fmaxf(mx, sp[tid][j]);
            float al = expf(sm_[tid] - mx);
            float sum = 0.f;
            #pragma unroll
            for (int j = 0; j < 32; ++j) { float p = expf(sp[tid][j]-mx); sp[tid][j] = p; sum += p; }
            sl_[tid] = sl_[tid]*al + sum;
            sm_[tid] = mx;
            sal[tid] = al;
        }
        __syncthreads();
        float a0 = sal[pr], a1 = sal[pr+1], a2 = sal[pr+2], a3 = sal[pr+3];
        #pragma unroll
        for (int j = 0; j < 4; ++j) { acc[0][j]*=a0; acc[1][j]*=a1; acc[2][j]*=a2; acc[3][j]*=a3; }
        #pragma unroll
        for (int kk = 0; kk < 32; ++kk) {
            float pv[4], vv[4];
            #pragma unroll
            for (int i = 0; i < 4; ++i) pv[i] = sp[pr+i][kk];
            #pragma unroll
            for (int j = 0; j < 4; ++j) vv[j] = sv[kk][pc+j];
            #pragma unroll
            for (int i = 0; i < 4; ++i)
                #pragma unroll
                for (int j = 0; j < 4; ++j) acc[i][j] += pv[i]*vv[j];
        }
        __syncthreads();
    }
    float gwv = g_gw[bt*Hc+h];
    float* ob = g_o + ((size_t)(bt*Lc))*Cc;
    #pragma unroll
    for (int i = 0; i < 4; ++i) {
        float inv = gwv / sl_[pr+i];
        #pragma unroll
        for (int j = 0; j < 4; ++j)
            ob[(size_t)(l0+pr+i)*Cc + h*HD + pc + j] = acc[i][j]*inv;
    }
}

// ---------------- residual + transpose back: out[b,c,t,l] -------------------
__global__ void k_resid(const float* __restrict__ x, float* __restrict__ out) {
    __shared__ float tile[32][33];
    int bt = blockIdx.z; int b = bt / Tc, t = bt % Tc;
    int l0 = blockIdx.x * 32, c0 = blockIdx.y * 32;
    const float* s = g_proj + (size_t)bt*Lc*Cc;
    int tx = threadIdx.x, ty = threadIdx.y;
    #pragma unroll
    for (int j = 0; j < 32; j += 8)
        tile[ty+j][tx] = s[(size_t)(l0+ty+j)*Cc + c0 + tx];
    __syncthreads();
    const float* xb = x + (size_t)b*CTL + (size_t)t*Lc;
    float*       ob = out + (size_t)b*CTL + (size_t)t*Lc;
    #pragma unroll
    for (int j = 0; j < 32; j += 8) {
        size_t idx = (size_t)(c0+ty+j)*TL + l0 + tx;
        ob[idx] = tile[tx][ty+j] + xb[idx];
    }
}

// ---------------- launcher --------------------------------------------------
extern "C" void kernel_launch(void* const* d_in, const int* in_sizes, int n_in,
                              void* d_out, int out_size) {
    const float* e   = (const float*)d_in[0];
    const float* x   = (const float*)d_in[1];
    const float* Wq  = (const float*)d_in[2];
    const float* bq  = (const float*)d_in[3];
    const float* Wkv = (const float*)d_in[4];
    const float* bkv = (const float*)d_in[5];
    const float* Wm  = (const float*)d_in[6];
    const float* bm  = (const float*)d_in[7];
    const float* Wg1 = (const float*)d_in[8];
    const float* bg1 = (const float*)d_in[9];
    const float* Wg2 = (const float*)d_in[10];
    const float* bg2 = (const float*)d_in[11];
    float* out = (float*)d_out;

    dim3 tb(32, 8);
    // transposes of e and x into (bt,l,c)
    k_transpose<<<dim3(Lc/32, Cc/32, BT), tb>>>(e, g_ept);
    k_transpose<<<dim3(Lc/32, Cc/32, BT), tb>>>(x, g_xpt);
    // pooled means (reads e directly, contiguous in l)
    k_pool<<< (BT*Cc*32 + 255)/256, 256 >>>(e);
    // gating weights
    k_gate<<<BT, Cc>>>(Wg1, bg1, Wg2, bg2);
    // projections
    k_sgemm_nt<<<dim3(4, 4, BT), 256>>>(0, Wq,  bq);   // Q
    k_sgemm_nt<<<dim3(8, 4, BT), 256>>>(1, Wkv, bkv);  // KV
    // normalizations
    k_norm_q <<< (BT*Lc*Hc*32 + 255)/256, 256 >>>();
    k_norm_kv<<< (BT*Lc*16*32 + 255)/256, 256 >>>();
    // attention
    k_attn<<<dim3(Lc/64, Hc, BT), 256>>>();
    // output projection
    k_sgemm_nt<<<dim3(4, 4, BT), 256>>>(2, Wm, bm);
    // residual + final transpose
    k_resid<<<dim3(Lc/32, Cc/32, BT), tb>>>(x, out);
}

// round 2
// speedup vs baseline: 1.5304x; 1.5304x over previous
#include <cuda_runtime.h>
#include <math.h>
#include <stdint.h>

#define Bc 4
#define Cc 512
#define Tc 8
#define Lc 512
#define Hc 8
#define HD 64
#define BT 32               // B*T
#define CTL (Cc*Tc*Lc)
#define TL  (Tc*Lc)

// ---------------- scratch (device globals; no allocation allowed) ----------
__device__ __align__(16) float g_ept  [(size_t)BT*Lc*Cc];     // e transposed  (bt,l,c)
__device__ __align__(16) float g_xpt  [(size_t)BT*Lc*Cc];     // x transposed  (bt,l,c)
__device__ __align__(16) float g_pooled[BT*Cc];
__device__ __align__(16) float g_gw   [BT*Hc];
__device__ __align__(16) float g_qraw [(size_t)BT*Lc*Cc];     // (bt,l,c)
__device__ __align__(16) float g_kvraw[(size_t)BT*Lc*2*Cc];   // (bt,l,2c)
__device__ __align__(16) float g_q    [(size_t)BT*Hc*Lc*HD];  // (bt,h,l,d)
__device__ __align__(16) float g_k    [(size_t)BT*Hc*Lc*HD];
__device__ __align__(16) float g_v    [(size_t)BT*Hc*Lc*HD];
__device__ __align__(16) float g_o    [(size_t)BT*Lc*Cc];     // attn out (bt,l,c)
__device__ __align__(16) float g_proj [(size_t)BT*Lc*Cc];     // out-proj (bt,l,c)

// ---------------- tf32 helpers ----------------------------------------------
__device__ __forceinline__ uint32_t f2tf32(float f) {
    uint32_t u;
    asm("cvt.rna.tf32.f32 %0, %1;" : "=r"(u) : "f"(f));
    return u;
}

__device__ __forceinline__ void mma_tf32(float c[4], const uint32_t a[4],
                                         uint32_t b0, uint32_t b1) {
    asm volatile(
        "mma.sync.aligned.m16n8k8.row.col.f32.tf32.tf32.f32 "
        "{%0,%1,%2,%3},{%4,%5,%6,%7},{%8,%9},{%0,%1,%2,%3};"
        : "+f"(c[0]), "+f"(c[1]), "+f"(c[2]), "+f"(c[3])
        : "r"(a[0]), "r"(a[1]), "r"(a[2]), "r"(a[3]), "r"(b0), "r"(b1));
}

// ---------------- transpose (b,c,t,l) -> (bt,l,c) --------------------------
__global__ void k_transpose(const float* __restrict__ src, float* __restrict__ dst) {
    __shared__ float tile[32][33];
    int bt = blockIdx.z;
    int b = bt / Tc, t = bt % Tc;
    int l0 = blockIdx.x * 32;
    int c0 = blockIdx.y * 32;
    const float* s = src + (size_t)b*CTL + (size_t)t*Lc;   // + c*TL + l
    int tx = threadIdx.x, ty = threadIdx.y;
    #pragma unroll
    for (int j = 0; j < 32; j += 8)
        tile[ty+j][tx] = s[(size_t)(c0+ty+j)*TL + l0 + tx];
    __syncthreads();
    float* d = dst + (size_t)bt*Lc*Cc;
    #pragma unroll
    for (int j = 0; j < 32; j += 8)
        d[(size_t)(l0+ty+j)*Cc + c0 + tx] = tile[tx][ty+j];
}

// ---------------- pooled[bt,c] = mean_l e[b,c,t,l] --------------------------
__global__ void k_pool(const float* __restrict__ e) {
    int w    = (blockIdx.x * blockDim.x + threadIdx.x) >> 5;
    int lane = threadIdx.x & 31;
    if (w >= BT*Cc) return;
    int bt = w / Cc, c = w % Cc;
    int b = bt / Tc, t = bt % Tc;
    const float* p = e + (size_t)b*CTL + (size_t)c*TL + (size_t)t*Lc;
    float s = 0.f;
    #pragma unroll 4
    for (int l = lane; l < Lc; l += 32) s += p[l];
    #pragma unroll
    for (int o = 16; o; o >>= 1) s += __shfl_xor_sync(0xffffffffu, s, o);
    if (!lane) g_pooled[w] = s * (1.0f/Lc);
}

// ---------------- gating: gw = softmax(tanh(pooled@Wg1^T+bg1)@Wg2^T+bg2) ----
// one block per bt, 512 threads = 16 warps; warp-per-output coalesced dots.
__global__ void __launch_bounds__(512) k_gate(
        const float* __restrict__ Wg1, const float* __restrict__ bg1,
        const float* __restrict__ Wg2, const float* __restrict__ bg2) {
    __shared__ float sp[Cc], sh1[Cc], sg[Hc];
    int bt = blockIdx.x;
    int tid = threadIdx.x;
    int warp = tid >> 5, lane = tid & 31;
    sp[tid] = g_pooled[bt*Cc + tid];
    __syncthreads();
    // each warp computes 32 hidden outputs with coalesced row reads
    for (int r = warp*32; r < warp*32 + 32; ++r) {
        const float4* wr = (const float4*)(Wg1 + (size_t)r*Cc);
        const float4* pp = (const float4*)sp;
        float a = 0.f;
        #pragma unroll
        for (int k = lane; k < Cc/4; k += 32) {
            float4 wv = wr[k]; float4 pv = pp[k];
            a += wv.x*pv.x + wv.y*pv.y + wv.z*pv.z + wv.w*pv.w;
        }
        #pragma unroll
        for (int o = 16; o; o >>= 1) a += __shfl_xor_sync(0xffffffffu, a, o);
        if (!lane) sh1[r] = tanhf(a + bg1[r]);
    }
    __syncthreads();
    if (warp < Hc) {
        const float* w2 = Wg2 + (size_t)warp*Cc;
        float a = 0.f;
        #pragma unroll 4
        for (int k = lane; k < Cc; k += 32) a += sh1[k]*w2[k];
        #pragma unroll
        for (int o = 16; o; o >>= 1) a += __shfl_xor_sync(0xffffffffu, a, o);
        if (!lane) sg[warp] = a + bg2[warp];
    }
    __syncthreads();
    if (tid == 0) {
        float mx = sg[0];
        #pragma unroll
        for (int h = 1; h < Hc; ++h) mx = fmaxf(mx, sg[h]);
        float ex[Hc], ssum = 0.f;
        #pragma unroll
        for (int h = 0; h < Hc; ++h) { ex[h] = expf(sg[h]-mx); ssum += ex[h]; }
        #pragma unroll
        for (int h = 0; h < Hc; ++h) g_gw[bt*Hc+h] = ex[h]/ssum;
    }
}

// ---------------- tf32 tensor-core GEMM -------------------------------------
// C[bt][m][n] = A[bt][m][:] . W[n][:] + bias[n]
// which: 0 = Q (A=g_ept, C=g_qraw, N=512)
//        1 = KV (A=g_xpt, C=g_kvraw, N=1024)
//        2 = proj (A=g_o, C=g_proj, N=512)
// Block tile 128x128, K-tile 32. 8 warps: warp grid 4(M) x 2(N), warp tile 32x64.
// Per warp: m16n8k8 tiles, 2(M) x 8(N), 4 K-steps per K-tile.
#define GP 36   // smem pitch (uint32 words): conflict-free for frag loads
__global__ void __launch_bounds__(256) k_gemm_tf32(int which,
        const float* __restrict__ W, const float* __restrict__ bias) {
    const float* A; float* Cm; int N;
    if      (which == 0) { A = g_ept; Cm = g_qraw;  N = 512;  }
    else if (which == 1) { A = g_xpt; Cm = g_kvraw; N = 1024; }
    else                 { A = g_o;   Cm = g_proj;  N = 512;  }

    __shared__ uint32_t sA[128][GP];
    __shared__ uint32_t sB[128][GP];

    int bt = blockIdx.z;
    const float* Ab = A + (size_t)bt * (Lc*Cc);
    float* Cb = Cm + (size_t)bt * Lc * N;
    int m0 = blockIdx.y * 128;
    int n0 = blockIdx.x * 128;
    int tid = threadIdx.x;
    int lane = tid & 31, wid = tid >> 5;
    int wm = (wid & 3) * 32;     // warp M offset in block
    int wn = (wid >> 2) * 64;    // warp N offset in block

    int lr = tid >> 3;           // 0..31: row within 32-row chunk
    int lc = (tid & 7) * 4;      // col 0,4,...,28

    float acc[2][8][4] = {};

    for (int k0 = 0; k0 < Cc; k0 += 32) {
        #pragma unroll
        for (int rr = 0; rr < 128; rr += 32) {
            float4 v = *(const float4*)(Ab + (size_t)(m0+rr+lr)*Cc + k0 + lc);
            uint4 u = make_uint4(f2tf32(v.x), f2tf32(v.y), f2tf32(v.z), f2tf32(v.w));
            *(uint4*)&sA[rr+lr][lc] = u;
        }
        #pragma unroll
        for (int rr = 0; rr < 128; rr += 32) {
            float4 v = *(const float4*)(W + (size_t)(n0+rr+lr)*Cc + k0 + lc);
            uint4 u = make_uint4(f2tf32(v.x), f2tf32(v.y), f2tf32(v.z), f2tf32(v.w));
            *(uint4*)&sB[rr+lr][lc] = u;
        }
        __syncthreads();
        #pragma unroll
        for (int ks = 0; ks < 32; ks += 8) {
            uint32_t af[2][4];
            int ar = lane >> 2, ac = ks + (lane & 3);
            #pragma unroll
            for (int i = 0; i < 2; ++i) {
                int r = wm + i*16 + ar;
                af[i][0] = sA[r  ][ac];
                af[i][1] = sA[r+8][ac];
                af[i][2] = sA[r  ][ac+4];
                af[i][3] = sA[r+8][ac+4];
            }
            #pragma unroll
            for (int j = 0; j < 8; ++j) {
                int bn = wn + j*8 + (lane >> 2);
                uint32_t b0 = sB[bn][ks + (lane & 3)];
                uint32_t b1 = sB[bn][ks + (lane & 3) + 4];
                #pragma unroll
                for (int i = 0; i < 2; ++i) mma_tf32(acc[i][j], af[i], b0, b1);
            }
        }
        __syncthreads();
    }
    // epilogue: C frag c0,c1 at (row=lane>>2, col=2*(lane&3)); c2,c3 at row+8
    int row = lane >> 2, col = (lane & 3) * 2;
    #pragma unroll
    for (int i = 0; i < 2; ++i) {
        #pragma unroll
        for (int j = 0; j < 8; ++j) {
            int gm = m0 + wm + i*16 + row;
            int gn = n0 + wn + j*8 + col;
            float b0 = bias[gn], b1 = bias[gn+1];
            *(float2*)&Cb[(size_t)gm*N + gn] =
                make_float2(acc[i][j][0] + b0, acc[i][j][1] + b1);
            *(float2*)&Cb[(size_t)(gm+8)*N + gn] =
                make_float2(acc[i][j][2] + b0, acc[i][j][3] + b1);
        }
    }
}

// ---------------- normalize Q rows (over hd=64) -----------------------------
__global__ void k_norm_q() {
    int w    = (blockIdx.x*blockDim.x + threadIdx.x) >> 5;   // one warp per (bt,l,h)
    int lane = threadIdx.x & 31;
    if (w >= BT*Lc*Hc) return;
    int h = w % Hc; int tmp = w / Hc; int l = tmp % Lc; int bt = tmp / Lc;
    const float* src = g_qraw + ((size_t)(bt*Lc + l))*Cc + h*HD;
    float v0 = src[lane], v1 = src[lane+32];
    float ss = v0*v0 + v1*v1;
    #pragma unroll
    for (int o = 16; o; o >>= 1) ss += __shfl_xor_sync(0xffffffffu, ss, o);
    float inv = 1.0f / fmaxf(sqrtf(ss), 1e-12f);
    float* dst = g_q + (((size_t)(bt*Hc + h))*Lc + l)*HD;
    dst[lane] = v0*inv; dst[lane+32] = v1*inv;
}

// ---------------- normalize K/V rows; V gets gw factor ----------------------
__global__ void k_norm_kv() {
    int w    = (blockIdx.x*blockDim.x + threadIdx.x) >> 5;   // warp per (bt,l,g)
    int lane = threadIdx.x & 31;
    if (w >= BT*Lc*16) return;
    int g = w % 16; int tmp = w / 16; int l = tmp % Lc; int bt = tmp / Lc;
    const float* src = g_kvraw + ((size_t)(bt*Lc + l))*(2*Cc) + g*HD;
    float v0 = src[lane], v1 = src[lane+32];
    float ss = v0*v0 + v1*v1;
    #pragma unroll
    for (int o = 16; o; o >>= 1) ss += __shfl_xor_sync(0xffffffffu, ss, o);
    float inv = 1.0f / fmaxf(sqrtf(ss), 1e-12f);
    if (g < Hc) {
        float* dst = g_k + (((size_t)(bt*Hc + g))*Lc + l)*HD;
        dst[lane] = v0*inv; dst[lane+32] = v1*inv;
    } else {
        int h = g - Hc;
        float s = inv * g_gw[bt*Hc + h];
        float* dst = g_v + (((size_t)(bt*Hc + h))*Lc + l)*HD;
        dst[lane] = v0*s; dst[lane+32] = v1*s;
    }
}

// ---------------- attention: per (bt,h), 64 q-rows / block, online softmax --
__global__ void __launch_bounds__(256) k_attn() {
    __shared__ float sq[64][65];
    __shared__ float sk[32][65];
    __shared__ float sv[32][65];
    __shared__ float sp[64][33];
    __shared__ float sm_[64], sl_[64], sal[64];
    int l0 = blockIdx.x * 64;
    int h  = blockIdx.y;
    int bt = blockIdx.z;
    int tid = threadIdx.x;
    const float* q  = g_q + ((size_t)(bt*Hc+h)*Lc)*HD;
    const float* kp = g_k + ((size_t)(bt*Hc+h)*Lc)*HD;
    const float* vp = g_v + ((size_t)(bt*Hc+h)*Lc)*HD;
    const float scale = 0.125f;                 // 1/sqrt(64)
    for (int i = tid; i < 64*64; i += 256) {
        int r = i >> 6, d = i & 63;
        sq[r][d] = q[(size_t)(l0+r)*HD + d] * scale;
    }
    if (tid < 64) { sm_[tid] = -1e30f; sl_[tid] = 0.f; }
    float acc[4][4] = {};
    int pr = (tid >> 4) * 4, pc = (tid & 15) * 4;   // PV mapping (64 x 64)
    int sr = (tid >> 4) * 4, sc = (tid & 15) * 2;   // S mapping  (64 x 32)
    __syncthreads();
    for (int jt = 0; jt < Lc; jt += 32) {
        for (int i = tid; i < 32*64; i += 256) {
            int r = i >> 6, d = i & 63;
            sk[r][d] = kp[(size_t)(jt+r)*HD + d];
            sv[r][d] = vp[(size_t)(jt+r)*HD + d];
        }
        __syncthreads();
        float s[4][2] = {};
        #pragma unroll
        for (int d = 0; d < 64; ++d) {
            float qr[4], kr[2];
            #pragma unroll
            for (int i = 0; i < 4; ++i) qr[i] = sq[sr+i][d];
            kr[0] = sk[sc][d]; kr[1] = sk[sc+1][d];
            #pragma unroll
            for (int i = 0; i < 4; ++i) { s[i][0] += qr[i]*kr[0]; s[i][1] += qr[i]*kr[1]; }
        }
        #pragma unroll
        for (int i = 0; i < 4; ++i) { sp[sr+i][sc] = s[i][0]; sp[sr+i][sc+1] = s[i][1]; }
        __syncthreads();
        if (tid < 64) {
            float mx = sm_[tid];
            #pragma unroll
            for (int j = 0; j < 32; ++j) mx = fmaxf(mx, sp[tid][j]);
            float al = expf(sm_[tid] - mx);
            float sum = 0.f;
            #pragma unroll
            for (int j = 0; j < 32; ++j) { float p = expf(sp[tid][j]-mx); sp[tid][j] = p; sum += p; }
            sl_[tid] = sl_[tid]*al + sum;
            sm_[tid] = mx;
            sal[tid] = al;
        }
        __syncthreads();
        float a0 = sal[pr], a1 = sal[pr+1], a2 = sal[pr+2], a3 = sal[pr+3];
        #pragma unroll
        for (int j = 0; j < 4; ++j) { acc[0][j]*=a0; acc[1][j]*=a1; acc[2][j]*=a2; acc[3][j]*=a3; }
        #pragma unroll
        for (int kk = 0; kk < 32; ++kk) {
            float pv[4], vv[4];
            #pragma unroll
            for (int i = 0; i < 4; ++i) pv[i] = sp[pr+i][kk];
            #pragma unroll
            for (int j = 0; j < 4; ++j) vv[j] = sv[kk][pc+j];
            #pragma unroll
            for (int i = 0; i < 4; ++i)
                #pragma unroll
                for (int j = 0; j < 4; ++j) acc[i][j] += pv[i]*vv[j];
        }
        __syncthreads();
    }
    float gwv = g_gw[bt*Hc+h];
    float* ob = g_o + ((size_t)(bt*Lc))*Cc;
    #pragma unroll
    for (int i = 0; i < 4; ++i) {
        float inv = gwv / sl_[pr+i];
        #pragma unroll
        for (int j = 0; j < 4; ++j)
            ob[(size_t)(l0+pr+i)*Cc + h*HD + pc + j] = acc[i][j]*inv;
    }
}

// ---------------- residual + transpose back: out[b,c,t,l] -------------------
__global__ void k_resid(const float* __restrict__ x, float* __restrict__ out) {
    __shared__ float tile[32][33];
    int bt = blockIdx.z; int b = bt / Tc, t = bt % Tc;
    int l0 = blockIdx.x * 32, c0 = blockIdx.y * 32;
    const float* s = g_proj + (size_t)bt*Lc*Cc;
    int tx = threadIdx.x, ty = threadIdx.y;
    #pragma unroll
    for (int j = 0; j < 32; j += 8)
        tile[ty+j][tx] = s[(size_t)(l0+ty+j)*Cc + c0 + tx];
    __syncthreads();
    const float* xb = x + (size_t)b*CTL + (size_t)t*Lc;
    float*       ob = out + (size_t)b*CTL + (size_t)t*Lc;
    #pragma unroll
    for (int j = 0; j < 32; j += 8) {
        size_t idx = (size_t)(c0+ty+j)*TL + l0 + tx;
        ob[idx] = tile[tx][ty+j] + xb[idx];
    }
}

// ---------------- launcher --------------------------------------------------
extern "C" void kernel_launch(void* const* d_in, const int* in_sizes, int n_in,
                              void* d_out, int out_size) {
    const float* e   = (const float*)d_in[0];
    const float* x   = (const float*)d_in[1];
    const float* Wq  = (const float*)d_in[2];
    const float* bq  = (const float*)d_in[3];
    const float* Wkv = (const float*)d_in[4];
    const float* bkv = (const float*)d_in[5];
    const float* Wm  = (const float*)d_in[6];
    const float* bm  = (const float*)d_in[7];
    const float* Wg1 = (const float*)d_in[8];
    const float* bg1 = (const float*)d_in[9];
    const float* Wg2 = (const float*)d_in[10];
    const float* bg2 = (const float*)d_in[11];
    float* out = (float*)d_out;

    dim3 tb(32, 8);
    // transposes of e and x into (bt,l,c)
    k_transpose<<<dim3(Lc/32, Cc/32, BT), tb>>>(e, g_ept);
    k_transpose<<<dim3(Lc/32, Cc/32, BT), tb>>>(x, g_xpt);
    // pooled means (reads e directly, contiguous in l)
    k_pool<<< (BT*Cc*32 + 255)/256, 256 >>>(e);
    // gating weights
    k_gate<<<BT, 512>>>(Wg1, bg1, Wg2, bg2);
    // projections (tf32 tensor cores)
    k_gemm_tf32<<<dim3(4, 4, BT), 256>>>(0, Wq,  bq);   // Q
    k_gemm_tf32<<<dim3(8, 4, BT), 256>>>(1, Wkv, bkv);  // KV
    // normalizations
    k_norm_q <<< (BT*Lc*Hc*32 + 255)/256, 256 >>>();
    k_norm_kv<<< (BT*Lc*16*32 + 255)/256, 256 >>>();
    // attention
    k_attn<<<dim3(Lc/64, Hc, BT), 256>>>();
    // output projection
    k_gemm_tf32<<<dim3(4, 4, BT), 256>>>(2, Wm, bm);
    // residual + final transpose
    k_resid<<<dim3(Lc/32, Cc/32, BT), tb>>>(x, out);
}

// round 3
// speedup vs baseline: 1.8823x; 1.2299x over previous
#include <cuda_runtime.h>
#include <cuda_bf16.h>
#include <math.h>
#include <stdint.h>

#define Bc 4
#define Cc 512
#define Tc 8
#define Lc 512
#define Hc 8
#define HD 64
#define BT 32               // B*T
#define CTL (Cc*Tc*Lc)
#define TL  (Tc*Lc)

// ---------------- scratch (device globals; no allocation allowed) ----------
__device__ __align__(16) float g_ept  [(size_t)BT*Lc*Cc];     // e transposed  (bt,l,c)
__device__ __align__(16) float g_xpt  [(size_t)BT*Lc*Cc];     // x transposed  (bt,l,c)
__device__ __align__(16) float g_pooled[BT*Cc];
__device__ __align__(16) float g_h1   [BT*Cc];                // gate hidden
__device__ __align__(16) float g_gw   [BT*Hc];
__device__ __align__(16) float g_qraw [(size_t)BT*Lc*Cc];     // (bt,l,c)
__device__ __align__(16) float g_kvraw[(size_t)BT*Lc*2*Cc];   // (bt,l,2c)
__device__ __align__(16) unsigned short g_qh[(size_t)BT*Hc*Lc*HD];  // bf16 (bt,h,l,d), 0.125 folded
__device__ __align__(16) unsigned short g_kh[(size_t)BT*Hc*Lc*HD];  // bf16
__device__ __align__(16) unsigned short g_vh[(size_t)BT*Hc*Lc*HD];  // bf16, gw folded
__device__ __align__(16) float g_o    [(size_t)BT*Lc*Cc];     // attn out (bt,l,c)
__device__ __align__(16) float g_proj [(size_t)BT*Lc*Cc];     // out-proj (bt,l,c)

// ---------------- mma helpers ----------------------------------------------
__device__ __forceinline__ uint32_t f2tf32(float f) {
    uint32_t u;
    asm("cvt.rna.tf32.f32 %0, %1;" : "=r"(u) : "f"(f));
    return u;
}
__device__ __forceinline__ void mma_tf32(float c[4], const uint32_t a[4],
                                         uint32_t b0, uint32_t b1) {
    asm volatile(
        "mma.sync.aligned.m16n8k8.row.col.f32.tf32.tf32.f32 "
        "{%0,%1,%2,%3},{%4,%5,%6,%7},{%8,%9},{%0,%1,%2,%3};"
        : "+f"(c[0]), "+f"(c[1]), "+f"(c[2]), "+f"(c[3])
        : "r"(a[0]), "r"(a[1]), "r"(a[2]), "r"(a[3]), "r"(b0), "r"(b1));
}
__device__ __forceinline__ void mma_bf16(float c[4], const uint32_t a[4],
                                         uint32_t b0, uint32_t b1) {
    asm volatile(
        "mma.sync.aligned.m16n8k16.row.col.f32.bf16.bf16.f32 "
        "{%0,%1,%2,%3},{%4,%5,%6,%7},{%8,%9},{%0,%1,%2,%3};"
        : "+f"(c[0]), "+f"(c[1]), "+f"(c[2]), "+f"(c[3])
        : "r"(a[0]), "r"(a[1]), "r"(a[2]), "r"(a[3]), "r"(b0), "r"(b1));
}
__device__ __forceinline__ uint32_t packbf(float lo, float hi) {
    uint32_t l = (uint32_t)__bfloat16_as_ushort(__float2bfloat16_rn(lo));
    uint32_t h = (uint32_t)__bfloat16_as_ushort(__float2bfloat16_rn(hi));
    return l | (h << 16);
}

// ---------------- transpose (b,c,t,l) -> (bt,l,c) --------------------------
__global__ void k_transpose(const float* __restrict__ src, float* __restrict__ dst) {
    __shared__ float tile[32][33];
    int bt = blockIdx.z;
    int b = bt / Tc, t = bt % Tc;
    int l0 = blockIdx.x * 32;
    int c0 = blockIdx.y * 32;
    const float* s = src + (size_t)b*CTL + (size_t)t*Lc;
    int tx = threadIdx.x, ty = threadIdx.y;
    #pragma unroll
    for (int j = 0; j < 32; j += 8)
        tile[ty+j][tx] = s[(size_t)(c0+ty+j)*TL + l0 + tx];
    __syncthreads();
    float* d = dst + (size_t)bt*Lc*Cc;
    #pragma unroll
    for (int j = 0; j < 32; j += 8)
        d[(size_t)(l0+ty+j)*Cc + c0 + tx] = tile[tx][ty+j];
}

// ---------------- pooled[bt,c] = mean_l e[b,c,t,l] --------------------------
__global__ void k_pool(const float* __restrict__ e) {
    int w    = (blockIdx.x * blockDim.x + threadIdx.x) >> 5;
    int lane = threadIdx.x & 31;
    if (w >= BT*Cc) return;
    int bt = w / Cc, c = w % Cc;
    int b = bt / Tc, t = bt % Tc;
    const float* p = e + (size_t)b*CTL + (size_t)c*TL + (size_t)t*Lc;
    float s = 0.f;
    #pragma unroll 4
    for (int l = lane; l < Lc; l += 32) s += p[l];
    #pragma unroll
    for (int o = 16; o; o >>= 1) s += __shfl_xor_sync(0xffffffffu, s, o);
    if (!lane) g_pooled[w] = s * (1.0f/Lc);
}

// ---------------- gate layer 1: h1 = tanh(pooled @ Wg1^T + bg1) -------------
// grid (4, BT): block computes 128 hidden rows; 8 warps x 16 rows each.
__global__ void __launch_bounds__(256) k_gate1(
        const float* __restrict__ Wg1, const float* __restrict__ bg1) {
    __shared__ float sp[Cc];
    int bt = blockIdx.y;
    int r0 = blockIdx.x * 128;
    int tid = threadIdx.x, warp = tid >> 5, lane = tid & 31;
    sp[tid] = g_pooled[bt*Cc + tid];
    sp[tid+256] = g_pooled[bt*Cc + tid + 256];
    __syncthreads();
    const float4* pp = (const float4*)sp;
    #pragma unroll
    for (int i = 0; i < 16; ++i) {
        int r = r0 + warp*16 + i;
        const float4* wr = (const float4*)(Wg1 + (size_t)r*Cc);
        float a = 0.f;
        #pragma unroll
        for (int k = lane; k < Cc/4; k += 32) {
            float4 wv = wr[k]; float4 pv = pp[k];
            a += wv.x*pv.x + wv.y*pv.y + wv.z*pv.z + wv.w*pv.w;
        }
        #pragma unroll
        for (int o = 16; o; o >>= 1) a += __shfl_xor_sync(0xffffffffu, a, o);
        if (!lane) g_h1[bt*Cc + r] = tanhf(a + bg1[r]);
    }
}

// ---------------- gate layer 2 + softmax ------------------------------------
__global__ void __launch_bounds__(256) k_gate2(
        const float* __restrict__ Wg2, const float* __restrict__ bg2) {
    __shared__ float sg[Hc];
    int bt = blockIdx.x;
    int tid = threadIdx.x, warp = tid >> 5, lane = tid & 31;
    if (warp < Hc) {
        const float4* w2 = (const float4*)(Wg2 + (size_t)warp*Cc);
        const float4* hp = (const float4*)(g_h1 + bt*Cc);
        float a = 0.f;
        #pragma unroll
        for (int k = lane; k < Cc/4; k += 32) {
            float4 wv = w2[k]; float4 hv = hp[k];
            a += wv.x*hv.x + wv.y*hv.y + wv.z*hv.z + wv.w*hv.w;
        }
        #pragma unroll
        for (int o = 16; o; o >>= 1) a += __shfl_xor_sync(0xffffffffu, a, o);
        if (!lane) sg[warp] = a + bg2[warp];
    }
    __syncthreads();
    if (tid == 0) {
        float mx = sg[0];
        #pragma unroll
        for (int h = 1; h < Hc; ++h) mx = fmaxf(mx, sg[h]);
        float ex[Hc], ssum = 0.f;
        #pragma unroll
        for (int h = 0; h < Hc; ++h) { ex[h] = expf(sg[h]-mx); ssum += ex[h]; }
        #pragma unroll
        for (int h = 0; h < Hc; ++h) g_gw[bt*Hc+h] = ex[h]/ssum;
    }
}

// ---------------- tf32 tensor-core GEMM -------------------------------------
#define GP 36
__global__ void __launch_bounds__(256) k_gemm_tf32(int which,
        const float* __restrict__ W, const float* __restrict__ bias) {
    const float* A; float* Cm; int N;
    if      (which == 0) { A = g_ept; Cm = g_qraw;  N = 512;  }
    else if (which == 1) { A = g_xpt; Cm = g_kvraw; N = 1024; }
    else                 { A = g_o;   Cm = g_proj;  N = 512;  }

    __shared__ uint32_t sA[128][GP];
    __shared__ uint32_t sB[128][GP];

    int bt = blockIdx.z;
    const float* Ab = A + (size_t)bt * (Lc*Cc);
    float* Cb = Cm + (size_t)bt * Lc * N;
    int m0 = blockIdx.y * 128;
    int n0 = blockIdx.x * 128;
    int tid = threadIdx.x;
    int lane = tid & 31, wid = tid >> 5;
    int wm = (wid & 3) * 32;
    int wn = (wid >> 2) * 64;
    int lr = tid >> 3;
    int lc = (tid & 7) * 4;

    float acc[2][8][4] = {};

    for (int k0 = 0; k0 < Cc; k0 += 32) {
        #pragma unroll
        for (int rr = 0; rr < 128; rr += 32) {
            float4 v = *(const float4*)(Ab + (size_t)(m0+rr+lr)*Cc + k0 + lc);
            uint4 u = make_uint4(f2tf32(v.x), f2tf32(v.y), f2tf32(v.z), f2tf32(v.w));
            *(uint4*)&sA[rr+lr][lc] = u;
        }
        #pragma unroll
        for (int rr = 0; rr < 128; rr += 32) {
            float4 v = *(const float4*)(W + (size_t)(n0+rr+lr)*Cc + k0 + lc);
            uint4 u = make_uint4(f2tf32(v.x), f2tf32(v.y), f2tf32(v.z), f2tf32(v.w));
            *(uint4*)&sB[rr+lr][lc] = u;
        }
        __syncthreads();
        #pragma unroll
        for (int ks = 0; ks < 32; ks += 8) {
            uint32_t af[2][4];
            int ar = lane >> 2, ac = ks + (lane & 3);
            #pragma unroll
            for (int i = 0; i < 2; ++i) {
                int r = wm + i*16 + ar;
                af[i][0] = sA[r  ][ac];
                af[i][1] = sA[r+8][ac];
                af[i][2] = sA[r  ][ac+4];
                af[i][3] = sA[r+8][ac+4];
            }
            #pragma unroll
            for (int j = 0; j < 8; ++j) {
                int bn = wn + j*8 + (lane >> 2);
                uint32_t b0 = sB[bn][ks + (lane & 3)];
                uint32_t b1 = sB[bn][ks + (lane & 3) + 4];
                #pragma unroll
                for (int i = 0; i < 2; ++i) mma_tf32(acc[i][j], af[i], b0, b1);
            }
        }
        __syncthreads();
    }
    int row = lane >> 2, col = (lane & 3) * 2;
    #pragma unroll
    for (int i = 0; i < 2; ++i) {
        #pragma unroll
        for (int j = 0; j < 8; ++j) {
            int gm = m0 + wm + i*16 + row;
            int gn = n0 + wn + j*8 + col;
            float b0 = bias[gn], b1 = bias[gn+1];
            *(float2*)&Cb[(size_t)gm*N + gn] =
                make_float2(acc[i][j][0] + b0, acc[i][j][1] + b1);
            *(float2*)&Cb[(size_t)(gm+8)*N + gn] =
                make_float2(acc[i][j][2] + b0, acc[i][j][3] + b1);
        }
    }
}

// ---------------- normalize Q rows -> bf16, fold 0.125 scale ----------------
__global__ void k_norm_q() {
    int w    = (blockIdx.x*blockDim.x + threadIdx.x) >> 5;
    int lane = threadIdx.x & 31;
    if (w >= BT*Lc*Hc) return;
    int h = w % Hc; int tmp = w / Hc; int l = tmp % Lc; int bt = tmp / Lc;
    const float* src = g_qraw + ((size_t)(bt*Lc + l))*Cc + h*HD;
    float v0 = src[lane], v1 = src[lane+32];
    float ss = v0*v0 + v1*v1;
    #pragma unroll
    for (int o = 16; o; o >>= 1) ss += __shfl_xor_sync(0xffffffffu, ss, o);
    float inv = 0.125f / fmaxf(sqrtf(ss), 1e-12f);   // 1/sqrt(hd) folded
    unsigned short* dst = g_qh + (((size_t)(bt*Hc + h))*Lc + l)*HD;
    dst[lane]    = __bfloat16_as_ushort(__float2bfloat16_rn(v0*inv));
    dst[lane+32] = __bfloat16_as_ushort(__float2bfloat16_rn(v1*inv));
}

// ---------------- normalize K/V rows -> bf16; V gets gw ---------------------
__global__ void k_norm_kv() {
    int w    = (blockIdx.x*blockDim.x + threadIdx.x) >> 5;
    int lane = threadIdx.x & 31;
    if (w >= BT*Lc*16) return;
    int g = w % 16; int tmp = w / 16; int l = tmp % Lc; int bt = tmp / Lc;
    const float* src = g_kvraw + ((size_t)(bt*Lc + l))*(2*Cc) + g*HD;
    float v0 = src[lane], v1 = src[lane+32];
    float ss = v0*v0 + v1*v1;
    #pragma unroll
    for (int o = 16; o; o >>= 1) ss += __shfl_xor_sync(0xffffffffu, ss, o);
    float inv = 1.0f / fmaxf(sqrtf(ss), 1e-12f);
    if (g < Hc) {
        unsigned short* dst = g_kh + (((size_t)(bt*Hc + g))*Lc + l)*HD;
        dst[lane]    = __bfloat16_as_ushort(__float2bfloat16_rn(v0*inv));
        dst[lane+32] = __bfloat16_as_ushort(__float2bfloat16_rn(v1*inv));
    } else {
        int h = g - Hc;
        float s = inv * g_gw[bt*Hc + h];
        unsigned short* dst = g_vh + (((size_t)(bt*Hc + h))*Lc + l)*HD;
        dst[lane]    = __bfloat16_as_ushort(__float2bfloat16_rn(v0*s));
        dst[lane+32] = __bfloat16_as_ushort(__float2bfloat16_rn(v1*s));
    }
}

// ---------------- flash attention with bf16 mma -----------------------------
// CTA: (bt, h, 128 q rows). 8 warps x 16 q rows. KV tiles of 64.
__global__ void __launch_bounds__(256) k_attn() {
    __shared__ __align__(16) unsigned short sq[128][72];   // pitch 36 words
    __shared__ __align__(16) unsigned short sk[64][72];
    __shared__ __align__(16) uint32_t svT[64][33];         // [d][kv pair], packed bf16x2
    int l0 = blockIdx.x * 128;
    int h  = blockIdx.y;
    int bt = blockIdx.z;
    int tid = threadIdx.x, lane = tid & 31, w = tid >> 5;
    const unsigned short* qp = g_qh + ((size_t)(bt*Hc+h)*Lc + l0)*HD;
    const unsigned short* kp = g_kh + ((size_t)(bt*Hc+h)*Lc)*HD;
    const unsigned short* vp = g_vh + ((size_t)(bt*Hc+h)*Lc)*HD;

    // load Q tile (128 x 64 bf16)
    for (int i = tid; i < 1024; i += 256) {
        int r = i >> 3, d0 = (i & 7) * 8;
        *(uint4*)&sq[r][d0] = *(const uint4*)(qp + (size_t)r*HD + d0);
    }

    float m0 = -1e30f, m1 = -1e30f, ls0 = 0.f, ls1 = 0.f;
    float o[8][4] = {};
    const uint32_t* sqw = (const uint32_t*)sq;
    const uint32_t* skw = (const uint32_t*)sk;
    int qr = w*16 + (lane >> 2);
    int cB = lane & 3;
    __syncthreads();

    for (int jt = 0; jt < Lc; jt += 64) {
        // K tile (64 x 64)
        for (int i = tid; i < 512; i += 256) {
            int r = i >> 3, d0 = (i & 7) * 8;
            *(uint4*)&sk[r][d0] = *(const uint4*)(kp + (size_t)(jt+r)*HD + d0);
        }
        // V tile, transposed + packed: svT[d][kv/2] = (v[kv][d], v[kv+1][d])
        {
            int kvp = tid >> 3, d0 = (tid & 7) * 8;
            uint4 u0 = *(const uint4*)(vp + (size_t)(jt + 2*kvp)*HD + d0);
            uint4 u1 = *(const uint4*)(vp + (size_t)(jt + 2*kvp + 1)*HD + d0);
            const unsigned short* a = (const unsigned short*)&u0;
            const unsigned short* b = (const unsigned short*)&u1;
            #pragma unroll
            for (int j = 0; j < 8; ++j)
                svT[d0+j][kvp] = (uint32_t)a[j] | ((uint32_t)b[j] << 16);
        }
        __syncthreads();

        // S = Q K^T  (16 x 64 per warp)
        float s[8][4] = {};
        #pragma unroll
        for (int ks = 0; ks < 4; ++ks) {
            uint32_t A[4];
            int ac = ks*8 + cB;
            A[0] = sqw[qr*36 + ac];
            A[1] = sqw[(qr+8)*36 + ac];
            A[2] = sqw[qr*36 + ac + 4];
            A[3] = sqw[(qr+8)*36 + ac + 4];
            #pragma unroll
            for (int n = 0; n < 8; ++n) {
                int kr = n*8 + (lane >> 2);
                uint32_t B0 = skw[kr*36 + ac];
                uint32_t B1 = skw[kr*36 + ac + 4];
                mma_bf16(s[n], A, B0, B1);
            }
        }

        // online softmax
        float mx0 = m0, mx1 = m1;
        #pragma unroll
        for (int n = 0; n < 8; ++n) {
            mx0 = fmaxf(mx0, fmaxf(s[n][0], s[n][1]));
            mx1 = fmaxf(mx1, fmaxf(s[n][2], s[n][3]));
        }
        #pragma unroll
        for (int off = 1; off <= 2; off <<= 1) {
            mx0 = fmaxf(mx0, __shfl_xor_sync(0xffffffffu, mx0, off));
            mx1 = fmaxf(mx1, __shfl_xor_sync(0xffffffffu, mx1, off));
        }
        float al0 = __expf(m0 - mx0), al1 = __expf(m1 - mx1);
        float rs0 = 0.f, rs1 = 0.f;
        #pragma unroll
        for (int n = 0; n < 8; ++n) {
            s[n][0] = __expf(s[n][0] - mx0);
            s[n][1] = __expf(s[n][1] - mx0);
            s[n][2] = __expf(s[n][2] - mx1);
            s[n][3] = __expf(s[n][3] - mx1);
            rs0 += s[n][0] + s[n][1];
            rs1 += s[n][2] + s[n][3];
        }
        #pragma unroll
        for (int off = 1; off <= 2; off <<= 1) {
            rs0 += __shfl_xor_sync(0xffffffffu, rs0, off);
            rs1 += __shfl_xor_sync(0xffffffffu, rs1, off);
        }
        ls0 = ls0*al0 + rs0;
        ls1 = ls1*al1 + rs1;
        m0 = mx0; m1 = mx1;
        #pragma unroll
        for (int j = 0; j < 8; ++j) {
            o[j][0] *= al0; o[j][1] *= al0; o[j][2] *= al1; o[j][3] *= al1;
        }

        // O += P V  (P frags -> A frags directly)
        #pragma unroll
        for (int kv = 0; kv < 4; ++kv) {
            uint32_t A[4];
            A[0] = packbf(s[2*kv][0],   s[2*kv][1]);
            A[1] = packbf(s[2*kv][2],   s[2*kv][3]);
            A[2] = packbf(s[2*kv+1][0], s[2*kv+1][1]);
            A[3] = packbf(s[2*kv+1][2], s[2*kv+1][3]);
            #pragma unroll
            for (int d = 0; d < 8; ++d) {
                int dr = d*8 + (lane >> 2);
                uint32_t B0 = svT[dr][kv*8 + cB];
                uint32_t B1 = svT[dr][kv*8 + cB + 4];
                mma_bf16(o[d], A, B0, B1);
            }
        }
        __syncthreads();
    }

    // epilogue
    float gwv = g_gw[bt*Hc + h];
    float i0 = gwv / ls0, i1 = gwv / ls1;
    int grow = bt*Lc + l0 + qr;
    int gcol = h*HD + (lane & 3)*2;
    #pragma unroll
    for (int d = 0; d < 8; ++d) {
        *(float2*)&g_o[(size_t)grow*Cc + gcol + d*8] =
            make_float2(o[d][0]*i0, o[d][1]*i0);
        *(float2*)&g_o[(size_t)(grow+8)*Cc + gcol + d*8] =
            make_float2(o[d][2]*i1, o[d][3]*i1);
    }
}

// ---------------- residual + transpose back: out[b,c,t,l] -------------------
__global__ void k_resid(const float* __restrict__ x, float* __restrict__ out) {
    __shared__ float tile[32][33];
    int bt = blockIdx.z; int b = bt / Tc, t = bt % Tc;
    int l0 = blockIdx.x * 32, c0 = blockIdx.y * 32;
    const float* s = g_proj + (size_t)bt*Lc*Cc;
    int tx = threadIdx.x, ty = threadIdx.y;
    #pragma unroll
    for (int j = 0; j < 32; j += 8)
        tile[ty+j][tx] = s[(size_t)(l0+ty+j)*Cc + c0 + tx];
    __syncthreads();
    const float* xb = x + (size_t)b*CTL + (size_t)t*Lc;
    float*       ob = out + (size_t)b*CTL + (size_t)t*Lc;
    #pragma unroll
    for (int j = 0; j < 32; j += 8) {
        size_t idx = (size_t)(c0+ty+j)*TL + l0 + tx;
        ob[idx] = tile[tx][ty+j] + xb[idx];
    }
}

// ---------------- launcher --------------------------------------------------
extern "C" void kernel_launch(void* const* d_in, const int* in_sizes, int n_in,
                              void* d_out, int out_size) {
    const float* e   = (const float*)d_in[0];
    const float* x   = (const float*)d_in[1];
    const float* Wq  = (const float*)d_in[2];
    const float* bq  = (const float*)d_in[3];
    const float* Wkv = (const float*)d_in[4];
    const float* bkv = (const float*)d_in[5];
    const float* Wm  = (const float*)d_in[6];
    const float* bm  = (const float*)d_in[7];
    const float* Wg1 = (const float*)d_in[8];
    const float* bg1 = (const float*)d_in[9];
    const float* Wg2 = (const float*)d_in[10];
    const float* bg2 = (const float*)d_in[11];
    float* out = (float*)d_out;

    dim3 tb(32, 8);
    k_transpose<<<dim3(Lc/32, Cc/32, BT), tb>>>(e, g_ept);
    k_transpose<<<dim3(Lc/32, Cc/32, BT), tb>>>(x, g_xpt);
    k_pool<<< (BT*Cc*32 + 255)/256, 256 >>>(e);
    k_gate1<<<dim3(4, BT), 256>>>(Wg1, bg1);
    k_gate2<<<BT, 256>>>(Wg2, bg2);
    k_gemm_tf32<<<dim3(4, 4, BT), 256>>>(0, Wq,  bq);   // Q
    k_gemm_tf32<<<dim3(8, 4, BT), 256>>>(1, Wkv, bkv);  // KV
    k_norm_q <<< (BT*Lc*Hc*32 + 255)/256, 256 >>>();
    k_norm_kv<<< (BT*Lc*16*32 + 255)/256, 256 >>>();
    k_attn<<<dim3(Lc/128, Hc, BT), 256>>>();
    k_gemm_tf32<<<dim3(4, 4, BT), 256>>>(2, Wm, bm);
    k_resid<<<dim3(Lc/32, Cc/32, BT), tb>>>(x, out);
}

// round 4
// speedup vs baseline: 4.4547x; 2.3666x over previous
#include <cuda_runtime.h>
#include <cuda_bf16.h>
#include <math.h>
#include <stdint.h>

#define Bc 4
#define Cc 512
#define Tc 8
#define Lc 512
#define Hc 8
#define HD 64
#define BT 32               // B*T
#define CTL (Cc*Tc*Lc)
#define TL  (Tc*Lc)

// ---------------- scratch (device globals; no allocation allowed) ----------
__device__ __align__(16) float g_pooled[BT*Cc];
__device__ __align__(16) float g_h1   [BT*Cc];
__device__ __align__(16) float g_gw   [BT*Hc];
__device__ __align__(16) float g_qraw [(size_t)BT*Lc*Cc];     // (bt,l,c)
__device__ __align__(16) float g_kvraw[(size_t)BT*Lc*2*Cc];   // (bt,l,2c)
__device__ __align__(16) unsigned short g_qh[(size_t)BT*Hc*Lc*HD];  // bf16, 0.125 folded
__device__ __align__(16) unsigned short g_kh[(size_t)BT*Hc*Lc*HD];  // bf16
__device__ __align__(16) unsigned short g_vh[(size_t)BT*Hc*Lc*HD];  // bf16, gw folded
__device__ __align__(16) float g_o    [(size_t)BT*Lc*Cc];     // attn out (bt,l,c)

// ---------------- helpers ---------------------------------------------------
__device__ __forceinline__ void mma_bf16(float c[4], const uint32_t a[4],
                                         uint32_t b0, uint32_t b1) {
    asm volatile(
        "mma.sync.aligned.m16n8k16.row.col.f32.bf16.bf16.f32 "
        "{%0,%1,%2,%3},{%4,%5,%6,%7},{%8,%9},{%0,%1,%2,%3};"
        : "+f"(c[0]), "+f"(c[1]), "+f"(c[2]), "+f"(c[3])
        : "r"(a[0]), "r"(a[1]), "r"(a[2]), "r"(a[3]), "r"(b0), "r"(b1));
}
__device__ __forceinline__ uint32_t packbf(float lo, float hi) {
    uint32_t r;
    asm("cvt.rn.bf16x2.f32 %0, %1, %2;" : "=r"(r) : "f"(hi), "f"(lo));
    return r;
}

// ---------------- pooled[bt,c] = mean_l e[b,c,t,l] --------------------------
__global__ void k_pool(const float* __restrict__ e) {
    int w    = (blockIdx.x * blockDim.x + threadIdx.x) >> 5;
    int lane = threadIdx.x & 31;
    if (w >= BT*Cc) return;
    int bt = w / Cc, c = w % Cc;
    int b = bt / Tc, t = bt % Tc;
    const float* p = e + (size_t)b*CTL + (size_t)c*TL + (size_t)t*Lc;
    float s = 0.f;
    #pragma unroll 4
    for (int l = lane; l < Lc; l += 32) s += p[l];
    #pragma unroll
    for (int o = 16; o; o >>= 1) s += __shfl_xor_sync(0xffffffffu, s, o);
    if (!lane) g_pooled[w] = s * (1.0f/Lc);
}

// ---------------- gate layer 1 ---------------------------------------------
__global__ void __launch_bounds__(256) k_gate1(
        const float* __restrict__ Wg1, const float* __restrict__ bg1) {
    __shared__ float sp[Cc];
    int bt = blockIdx.y;
    int r0 = blockIdx.x * 128;
    int tid = threadIdx.x, warp = tid >> 5, lane = tid & 31;
    sp[tid] = g_pooled[bt*Cc + tid];
    sp[tid+256] = g_pooled[bt*Cc + tid + 256];
    __syncthreads();
    const float4* pp = (const float4*)sp;
    #pragma unroll
    for (int i = 0; i < 16; ++i) {
        int r = r0 + warp*16 + i;
        const float4* wr = (const float4*)(Wg1 + (size_t)r*Cc);
        float a = 0.f;
        #pragma unroll
        for (int k = lane; k < Cc/4; k += 32) {
            float4 wv = wr[k]; float4 pv = pp[k];
            a += wv.x*pv.x + wv.y*pv.y + wv.z*pv.z + wv.w*pv.w;
        }
        #pragma unroll
        for (int o = 16; o; o >>= 1) a += __shfl_xor_sync(0xffffffffu, a, o);
        if (!lane) g_h1[bt*Cc + r] = tanhf(a + bg1[r]);
    }
}

// ---------------- gate layer 2 + softmax ------------------------------------
__global__ void __launch_bounds__(256) k_gate2(
        const float* __restrict__ Wg2, const float* __restrict__ bg2) {
    __shared__ float sg[Hc];
    int bt = blockIdx.x;
    int tid = threadIdx.x, warp = tid >> 5, lane = tid & 31;
    if (warp < Hc) {
        const float4* w2 = (const float4*)(Wg2 + (size_t)warp*Cc);
        const float4* hp = (const float4*)(g_h1 + bt*Cc);
        float a = 0.f;
        #pragma unroll
        for (int k = lane; k < Cc/4; k += 32) {
            float4 wv = w2[k]; float4 hv = hp[k];
            a += wv.x*hv.x + wv.y*hv.y + wv.z*hv.z + wv.w*hv.w;
        }
        #pragma unroll
        for (int o = 16; o; o >>= 1) a += __shfl_xor_sync(0xffffffffu, a, o);
        if (!lane) sg[warp] = a + bg2[warp];
    }
    __syncthreads();
    if (tid == 0) {
        float mx = sg[0];
        #pragma unroll
        for (int h = 1; h < Hc; ++h) mx = fmaxf(mx, sg[h]);
        float ex[Hc], ssum = 0.f;
        #pragma unroll
        for (int h = 0; h < Hc; ++h) { ex[h] = expf(sg[h]-mx); ssum += ex[h]; }
        #pragma unroll
        for (int h = 0; h < Hc; ++h) g_gw[bt*Hc+h] = ex[h]/ssum;
    }
}

// ---------------- bf16 tensor-core GEMM -------------------------------------
// which 0: A = transpose-load of e, C = g_qraw,  N=512
// which 1: A = transpose-load of x, C = g_kvraw, N=1024
// which 2: A = g_o (direct),        C = out (fused +x residual, transposed)
// Block tile 128x128, K-tile 32. 8 warps: 4(M) x 2(N), warp tile 32x64.
#define GPW 20   // smem word pitch, conflict-free fragment loads
__global__ void __launch_bounds__(256) k_gemm_bf16(int which,
        const float* __restrict__ W, const float* __restrict__ bias,
        const float* __restrict__ src,   // e (0) / x (1) / x for residual (2)
        float* __restrict__ outp) {      // out for which==2
    float* Cm = nullptr; int N = 512;
    if      (which == 0) { Cm = g_qraw;  N = 512;  }
    else if (which == 1) { Cm = g_kvraw; N = 1024; }

    __shared__ uint32_t sA[128][GPW];
    __shared__ uint32_t sB[128][GPW];
    __shared__ float    stage[4608];   // 32x132 transpose-stage | 128x36 epilogue

    int bt = blockIdx.z;
    int b = bt / Tc, t = bt % Tc;
    int m0 = blockIdx.y * 128;
    int n0 = blockIdx.x * 128;
    int tid = threadIdx.x, lane = tid & 31, wid = tid >> 5;
    int wm = (wid & 3) * 32;
    int wn = (wid >> 2) * 64;

    const float* tbase = src + (size_t)b*CTL + (size_t)t*Lc;   // (which<2) A source
    const float* Ab    = g_o + (size_t)bt*Lc*Cc;               // (which==2)

    int r8 = tid >> 3;          // 0..31
    int c8 = (tid & 7) * 4;     // 0,4..28

    float acc[2][8][4] = {};

    for (int k0 = 0; k0 < Cc; k0 += 32) {
        // ---- B tile: W[n0+n][k0+..]  (row-major, k-pairs pack directly) ----
        #pragma unroll
        for (int i = 0; i < 4; ++i) {
            int n = r8 + i*32;
            float4 v = *(const float4*)(W + (size_t)(n0+n)*Cc + k0 + c8);
            sB[n][(c8>>1)]   = packbf(v.x, v.y);
            sB[n][(c8>>1)+1] = packbf(v.z, v.w);
        }
        if (which == 2) {
            #pragma unroll
            for (int i = 0; i < 4; ++i) {
                int m = r8 + i*32;
                float4 v = *(const float4*)(Ab + (size_t)(m0+m)*Cc + k0 + c8);
                sA[m][(c8>>1)]   = packbf(v.x, v.y);
                sA[m][(c8>>1)+1] = packbf(v.z, v.w);
            }
            __syncthreads();
        } else {
            // A[m=l][k=c] = src[b][k0+r][t][m0+j]: 32 c-rows x 128 l-cols, coalesced
            #pragma unroll
            for (int i = 0; i < 4; ++i) {
                int j = (tid & 7)*4 + i*32;
                *(float4*)&stage[r8*132 + j] =
                    *(const float4*)(tbase + (size_t)(k0+r8)*TL + m0 + j);
            }
            __syncthreads();
            {   // pack transposed: sA[m][kw] = (stage[2kw][m], stage[2kw+1][m])
                int m = tid >> 1;
                int kw0 = (tid & 1) * 8;
                #pragma unroll
                for (int i = 0; i < 8; ++i) {
                    int kw = kw0 + i;
                    sA[m][kw] = packbf(stage[(2*kw)*132 + m], stage[(2*kw+1)*132 + m]);
                }
            }
            __syncthreads();
        }
        // ---- mma: 2 k16 steps ----
        #pragma unroll
        for (int ks = 0; ks < 2; ++ks) {
            uint32_t a[2][4];
            int kw = ks*8 + (lane & 3);
            #pragma unroll
            for (int i = 0; i < 2; ++i) {
                int r = wm + i*16 + (lane >> 2);
                a[i][0] = sA[r][kw];
                a[i][1] = sA[r+8][kw];
                a[i][2] = sA[r][kw+4];
                a[i][3] = sA[r+8][kw+4];
            }
            #pragma unroll
            for (int j = 0; j < 8; ++j) {
                int n = wn + j*8 + (lane >> 2);
                uint32_t b0 = sB[n][kw];
                uint32_t b1 = sB[n][kw+4];
                #pragma unroll
                for (int i = 0; i < 2; ++i) mma_bf16(acc[i][j], a[i], b0, b1);
            }
        }
        __syncthreads();
    }

    int row = lane >> 2, col = (lane & 3) * 2;
    if (which < 2) {
        float* Cb = Cm + (size_t)bt * Lc * N;
        #pragma unroll
        for (int i = 0; i < 2; ++i) {
            #pragma unroll
            for (int j = 0; j < 8; ++j) {
                int gm = m0 + wm + i*16 + row;
                int gn = n0 + wn + j*8 + col;
                float b0 = bias[gn], b1 = bias[gn+1];
                *(float2*)&Cb[(size_t)gm*N + gn] =
                    make_float2(acc[i][j][0] + b0, acc[i][j][1] + b1);
                *(float2*)&Cb[(size_t)(gm+8)*N + gn] =
                    make_float2(acc[i][j][2] + b0, acc[i][j][3] + b1);
            }
        }
    } else {
        // fused: out[b][c=n][t][l=m] = acc + bias[n] + x[b][c][t][l]
        // 4 passes over 32-row m-groups via smem transpose (pitch 36)
        for (int p = 0; p < 4; ++p) {
            __syncthreads();
            if ((wid & 3) == p) {
                #pragma unroll
                for (int i = 0; i < 2; ++i) {
                    #pragma unroll
                    for (int j = 0; j < 8; ++j) {
                        int n  = wn + j*8 + col;
                        int ml = i*16 + row;
                        float b0 = bias[n0+n], b1 = bias[n0+n+1];
                        stage[n*36 + ml]        = acc[i][j][0] + b0;
                        stage[(n+1)*36 + ml]    = acc[i][j][1] + b1;
                        stage[n*36 + ml + 8]    = acc[i][j][2] + b0;
                        stage[(n+1)*36 + ml + 8]= acc[i][j][3] + b1;
                    }
                }
            }
            __syncthreads();
            #pragma unroll
            for (int i = 0; i < 4; ++i) {
                int n  = r8 + i*32;
                int mm = (tid & 7) * 4;
                size_t gidx = (size_t)b*CTL + (size_t)(n0+n)*TL
                            + (size_t)t*Lc + m0 + p*32 + mm;
                float4 xv = *(const float4*)(src + gidx);
                float4 pv = *(float4*)&stage[n*36 + mm];
                *(float4*)&outp[gidx] =
                    make_float4(pv.x+xv.x, pv.y+xv.y, pv.z+xv.z, pv.w+xv.w);
            }
        }
    }
}

// ---------------- normalize Q rows -> bf16, fold 0.125 ----------------------
__global__ void k_norm_q() {
    int w    = (blockIdx.x*blockDim.x + threadIdx.x) >> 5;
    int lane = threadIdx.x & 31;
    if (w >= BT*Lc*Hc) return;
    int h = w % Hc; int tmp = w / Hc; int l = tmp % Lc; int bt = tmp / Lc;
    const float* src = g_qraw + ((size_t)(bt*Lc + l))*Cc + h*HD;
    float v0 = src[lane], v1 = src[lane+32];
    float ss = v0*v0 + v1*v1;
    #pragma unroll
    for (int o = 16; o; o >>= 1) ss += __shfl_xor_sync(0xffffffffu, ss, o);
    float inv = 0.125f / fmaxf(sqrtf(ss), 1e-12f);
    unsigned short* dst = g_qh + (((size_t)(bt*Hc + h))*Lc + l)*HD;
    dst[lane]    = __bfloat16_as_ushort(__float2bfloat16_rn(v0*inv));
    dst[lane+32] = __bfloat16_as_ushort(__float2bfloat16_rn(v1*inv));
}

// ---------------- normalize K/V rows -> bf16; V gets gw ---------------------
__global__ void k_norm_kv() {
    int w    = (blockIdx.x*blockDim.x + threadIdx.x) >> 5;
    int lane = threadIdx.x & 31;
    if (w >= BT*Lc*16) return;
    int g = w % 16; int tmp = w / 16; int l = tmp % Lc; int bt = tmp / Lc;
    const float* src = g_kvraw + ((size_t)(bt*Lc + l))*(2*Cc) + g*HD;
    float v0 = src[lane], v1 = src[lane+32];
    float ss = v0*v0 + v1*v1;
    #pragma unroll
    for (int o = 16; o; o >>= 1) ss += __shfl_xor_sync(0xffffffffu, ss, o);
    float inv = 1.0f / fmaxf(sqrtf(ss), 1e-12f);
    if (g < Hc) {
        unsigned short* dst = g_kh + (((size_t)(bt*Hc + g))*Lc + l)*HD;
        dst[lane]    = __bfloat16_as_ushort(__float2bfloat16_rn(v0*inv));
        dst[lane+32] = __bfloat16_as_ushort(__float2bfloat16_rn(v1*inv));
    } else {
        int h = g - Hc;
        float s = inv * g_gw[bt*Hc + h];
        unsigned short* dst = g_vh + (((size_t)(bt*Hc + h))*Lc + l)*HD;
        dst[lane]    = __bfloat16_as_ushort(__float2bfloat16_rn(v0*s));
        dst[lane+32] = __bfloat16_as_ushort(__float2bfloat16_rn(v1*s));
    }
}

// ---------------- flash attention with bf16 mma -----------------------------
__global__ void __launch_bounds__(256) k_attn() {
    __shared__ __align__(16) unsigned short sq[128][72];
    __shared__ __align__(16) unsigned short sk[64][72];
    __shared__ __align__(16) uint32_t svT[64][33];
    int l0 = blockIdx.x * 128;
    int h  = blockIdx.y;
    int bt = blockIdx.z;
    int tid = threadIdx.x, lane = tid & 31, w = tid >> 5;
    const unsigned short* qp = g_qh + ((size_t)(bt*Hc+h)*Lc + l0)*HD;
    const unsigned short* kp = g_kh + ((size_t)(bt*Hc+h)*Lc)*HD;
    const unsigned short* vp = g_vh + ((size_t)(bt*Hc+h)*Lc)*HD;

    for (int i = tid; i < 1024; i += 256) {
        int r = i >> 3, d0 = (i & 7) * 8;
        *(uint4*)&sq[r][d0] = *(const uint4*)(qp + (size_t)r*HD + d0);
    }

    float m0 = -1e30f, m1 = -1e30f, ls0 = 0.f, ls1 = 0.f;
    float o[8][4] = {};
    const uint32_t* sqw = (const uint32_t*)sq;
    const uint32_t* skw = (const uint32_t*)sk;
    int qr = w*16 + (lane >> 2);
    int cB = lane & 3;
    __syncthreads();

    for (int jt = 0; jt < Lc; jt += 64) {
        for (int i = tid; i < 512; i += 256) {
            int r = i >> 3, d0 = (i & 7) * 8;
            *(uint4*)&sk[r][d0] = *(const uint4*)(kp + (size_t)(jt+r)*HD + d0);
        }
        {
            int kvp = tid >> 3, d0 = (tid & 7) * 8;
            uint4 u0 = *(const uint4*)(vp + (size_t)(jt + 2*kvp)*HD + d0);
            uint4 u1 = *(const uint4*)(vp + (size_t)(jt + 2*kvp + 1)*HD + d0);
            const unsigned short* a = (const unsigned short*)&u0;
            const unsigned short* b = (const unsigned short*)&u1;
            #pragma unroll
            for (int j = 0; j < 8; ++j)
                svT[d0+j][kvp] = (uint32_t)a[j] | ((uint32_t)b[j] << 16);
        }
        __syncthreads();

        float s[8][4] = {};
        #pragma unroll
        for (int ks = 0; ks < 4; ++ks) {
            uint32_t A[4];
            int ac = ks*8 + cB;
            A[0] = sqw[qr*36 + ac];
            A[1] = sqw[(qr+8)*36 + ac];
            A[2] = sqw[qr*36 + ac + 4];
            A[3] = sqw[(qr+8)*36 + ac + 4];
            #pragma unroll
            for (int n = 0; n < 8; ++n) {
                int kr = n*8 + (lane >> 2);
                mma_bf16(s[n], A, skw[kr*36 + ac], skw[kr*36 + ac + 4]);
            }
        }

        float mx0 = m0, mx1 = m1;
        #pragma unroll
        for (int n = 0; n < 8; ++n) {
            mx0 = fmaxf(mx0, fmaxf(s[n][0], s[n][1]));
            mx1 = fmaxf(mx1, fmaxf(s[n][2], s[n][3]));
        }
        #pragma unroll
        for (int off = 1; off <= 2; off <<= 1) {
            mx0 = fmaxf(mx0, __shfl_xor_sync(0xffffffffu, mx0, off));
            mx1 = fmaxf(mx1, __shfl_xor_sync(0xffffffffu, mx1, off));
        }
        float al0 = __expf(m0 - mx0), al1 = __expf(m1 - mx1);
        float rs0 = 0.f, rs1 = 0.f;
        #pragma unroll
        for (int n = 0; n < 8; ++n) {
            s[n][0] = __expf(s[n][0] - mx0);
            s[n][1] = __expf(s[n][1] - mx0);
            s[n][2] = __expf(s[n][2] - mx1);
            s[n][3] = __expf(s[n][3] - mx1);
            rs0 += s[n][0] + s[n][1];
            rs1 += s[n][2] + s[n][3];
        }
        #pragma unroll
        for (int off = 1; off <= 2; off <<= 1) {
            rs0 += __shfl_xor_sync(0xffffffffu, rs0, off);
            rs1 += __shfl_xor_sync(0xffffffffu, rs1, off);
        }
        ls0 = ls0*al0 + rs0;
        ls1 = ls1*al1 + rs1;
        m0 = mx0; m1 = mx1;
        #pragma unroll
        for (int j = 0; j < 8; ++j) {
            o[j][0] *= al0; o[j][1] *= al0; o[j][2] *= al1; o[j][3] *= al1;
        }
        #pragma unroll
        for (int kv = 0; kv < 4; ++kv) {
            uint32_t A[4];
            A[0] = packbf(s[2*kv][0],   s[2*kv][1]);
            A[1] = packbf(s[2*kv][2],   s[2*kv][3]);
            A[2] = packbf(s[2*kv+1][0], s[2*kv+1][1]);
            A[3] = packbf(s[2*kv+1][2], s[2*kv+1][3]);
            #pragma unroll
            for (int d = 0; d < 8; ++d) {
                int dr = d*8 + (lane >> 2);
                mma_bf16(o[d], A, svT[dr][kv*8 + cB], svT[dr][kv*8 + cB + 4]);
            }
        }
        __syncthreads();
    }

    float gwv = g_gw[bt*Hc + h];
    float i0 = gwv / ls0, i1 = gwv / ls1;
    int grow = bt*Lc + l0 + qr;
    int gcol = h*HD + (lane & 3)*2;
    #pragma unroll
    for (int d = 0; d < 8; ++d) {
        *(float2*)&g_o[(size_t)grow*Cc + gcol + d*8] =
            make_float2(o[d][0]*i0, o[d][1]*i0);
        *(float2*)&g_o[(size_t)(grow+8)*Cc + gcol + d*8] =
            make_float2(o[d][2]*i1, o[d][3]*i1);
    }
}

// ---------------- launcher --------------------------------------------------
extern "C" void kernel_launch(void* const* d_in, const int* in_sizes, int n_in,
                              void* d_out, int out_size) {
    const float* e   = (const float*)d_in[0];
    const float* x   = (const float*)d_in[1];
    const float* Wq  = (const float*)d_in[2];
    const float* bq  = (const float*)d_in[3];
    const float* Wkv = (const float*)d_in[4];
    const float* bkv = (const float*)d_in[5];
    const float* Wm  = (const float*)d_in[6];
    const float* bm  = (const float*)d_in[7];
    const float* Wg1 = (const float*)d_in[8];
    const float* bg1 = (const float*)d_in[9];
    const float* Wg2 = (const float*)d_in[10];
    const float* bg2 = (const float*)d_in[11];
    float* out = (float*)d_out;

    k_pool<<< (BT*Cc*32 + 255)/256, 256 >>>(e);
    k_gate1<<<dim3(4, BT), 256>>>(Wg1, bg1);
    k_gate2<<<BT, 256>>>(Wg2, bg2);
    k_gemm_bf16<<<dim3(4, 4, BT), 256>>>(0, Wq,  bq,  e, nullptr);   // Q
    k_gemm_bf16<<<dim3(8, 4, BT), 256>>>(1, Wkv, bkv, x, nullptr);   // KV
    k_norm_q <<< (BT*Lc*Hc*32 + 255)/256, 256 >>>();
    k_norm_kv<<< (BT*Lc*16*32 + 255)/256, 256 >>>();
    k_attn<<<dim3(Lc/128, Hc, BT), 256>>>();
    k_gemm_bf16<<<dim3(4, 4, BT), 256>>>(2, Wm, bm, x, out);         // proj+resid
}

// round 5
// speedup vs baseline: 6.0399x; 1.3559x over previous
#include <cuda_runtime.h>
#include <cuda_bf16.h>
#include <math.h>
#include <stdint.h>

#define Bc 4
#define Cc 512
#define Tc 8
#define Lc 512
#define Hc 8
#define HD 64
#define BT 32               // B*T
#define CTL (Cc*Tc*Lc)
#define TL  (Tc*Lc)
#define SAP 20              // GEMM smem word pitch (bf16x2 words)

// ---------------- scratch (device globals; no allocation allowed) ----------
__device__ __align__(16) float g_pooled[BT*Cc];
__device__ __align__(16) float g_h1   [BT*Cc];
__device__ __align__(16) float g_gw   [BT*Hc];
__device__ __align__(16) unsigned short g_qh[(size_t)BT*Hc*Lc*HD];  // bf16, 0.125 folded
__device__ __align__(16) unsigned short g_kh[(size_t)BT*Hc*Lc*HD];  // bf16
__device__ __align__(16) unsigned short g_vh[(size_t)BT*Hc*Lc*HD];  // bf16, gw folded
__device__ __align__(16) float g_o    [(size_t)BT*Lc*Cc];           // attn out (bt,l,c)

// ---------------- helpers ---------------------------------------------------
__device__ __forceinline__ void mma_bf16(float c[4], const uint32_t a[4],
                                         uint32_t b0, uint32_t b1) {
    asm volatile(
        "mma.sync.aligned.m16n8k16.row.col.f32.bf16.bf16.f32 "
        "{%0,%1,%2,%3},{%4,%5,%6,%7},{%8,%9},{%0,%1,%2,%3};"
        : "+f"(c[0]), "+f"(c[1]), "+f"(c[2]), "+f"(c[3])
        : "r"(a[0]), "r"(a[1]), "r"(a[2]), "r"(a[3]), "r"(b0), "r"(b1));
}
__device__ __forceinline__ uint32_t packbf(float lo, float hi) {
    uint32_t r;
    asm("cvt.rn.bf16x2.f32 %0, %1, %2;" : "=r"(r) : "f"(hi), "f"(lo));
    return r;
}
__device__ __forceinline__ void ldsm4(uint32_t a[4], uint32_t addr) {
    asm volatile("ldmatrix.sync.aligned.m8n8.x4.shared.b16 {%0,%1,%2,%3}, [%4];"
        : "=r"(a[0]), "=r"(a[1]), "=r"(a[2]), "=r"(a[3]) : "r"(addr));
}
__device__ __forceinline__ uint32_t smem_u32(const void* p) {
    return (uint32_t)__cvta_generic_to_shared(p);
}

// ---------------- pooled[bt,c] = mean_l e[b,c,t,l] --------------------------
__global__ void k_pool(const float* __restrict__ e) {
    int w    = (blockIdx.x * blockDim.x + threadIdx.x) >> 5;
    int lane = threadIdx.x & 31;
    if (w >= BT*Cc) return;
    int bt = w / Cc, c = w % Cc;
    int b = bt / Tc, t = bt % Tc;
    const float* p = e + (size_t)b*CTL + (size_t)c*TL + (size_t)t*Lc;
    float s = 0.f;
    #pragma unroll 4
    for (int l = lane; l < Lc; l += 32) s += p[l];
    #pragma unroll
    for (int o = 16; o; o >>= 1) s += __shfl_xor_sync(0xffffffffu, s, o);
    if (!lane) g_pooled[w] = s * (1.0f/Lc);
}

// ---------------- gate layer 1 ---------------------------------------------
__global__ void __launch_bounds__(256) k_gate1(
        const float* __restrict__ Wg1, const float* __restrict__ bg1) {
    __shared__ float sp[Cc];
    int bt = blockIdx.y;
    int r0 = blockIdx.x * 128;
    int tid = threadIdx.x, warp = tid >> 5, lane = tid & 31;
    sp[tid] = g_pooled[bt*Cc + tid];
    sp[tid+256] = g_pooled[bt*Cc + tid + 256];
    __syncthreads();
    const float4* pp = (const float4*)sp;
    #pragma unroll
    for (int i = 0; i < 16; ++i) {
        int r = r0 + warp*16 + i;
        const float4* wr = (const float4*)(Wg1 + (size_t)r*Cc);
        float a = 0.f;
        #pragma unroll
        for (int k = lane; k < Cc/4; k += 32) {
            float4 wv = wr[k]; float4 pv = pp[k];
            a += wv.x*pv.x + wv.y*pv.y + wv.z*pv.z + wv.w*pv.w;
        }
        #pragma unroll
        for (int o = 16; o; o >>= 1) a += __shfl_xor_sync(0xffffffffu, a, o);
        if (!lane) g_h1[bt*Cc + r] = tanhf(a + bg1[r]);
    }
}

// ---------------- gate layer 2 + softmax ------------------------------------
__global__ void __launch_bounds__(256) k_gate2(
        const float* __restrict__ Wg2, const float* __restrict__ bg2) {
    __shared__ float sg[Hc];
    int bt = blockIdx.x;
    int tid = threadIdx.x, warp = tid >> 5, lane = tid & 31;
    if (warp < Hc) {
        const float4* w2 = (const float4*)(Wg2 + (size_t)warp*Cc);
        const float4* hp = (const float4*)(g_h1 + bt*Cc);
        float a = 0.f;
        #pragma unroll
        for (int k = lane; k < Cc/4; k += 32) {
            float4 wv = w2[k]; float4 hv = hp[k];
            a += wv.x*hv.x + wv.y*hv.y + wv.z*hv.z + wv.w*hv.w;
        }
        #pragma unroll
        for (int o = 16; o; o >>= 1) a += __shfl_xor_sync(0xffffffffu, a, o);
        if (!lane) sg[warp] = a + bg2[warp];
    }
    __syncthreads();
    if (tid == 0) {
        float mx = sg[0];
        #pragma unroll
        for (int h = 1; h < Hc; ++h) mx = fmaxf(mx, sg[h]);
        float ex[Hc], ssum = 0.f;
        #pragma unroll
        for (int h = 0; h < Hc; ++h) { ex[h] = expf(sg[h]-mx); ssum += ex[h]; }
        #pragma unroll
        for (int h = 0; h < Hc; ++h) g_gw[bt*Hc+h] = ex[h]/ssum;
    }
}

// ---------------- bf16 tensor-core GEMM (ldmatrix + prefetch) ---------------
// which 0: A = transpose-load of e, fused q-norm epilogue -> g_qh
// which 1: A = transpose-load of x, fused k/v-norm epilogue -> g_kh/g_vh
// which 2: A = g_o, fused residual+transpose epilogue -> out
__global__ void __launch_bounds__(256, 2) k_gemm_bf16(int which,
        const float* __restrict__ W, const float* __restrict__ bias,
        const float* __restrict__ src, float* __restrict__ outp) {
    __shared__ __align__(16) unsigned char smem[38912];
    uint32_t* sAw = (uint32_t*)smem;                    // [128][SAP]
    uint32_t* sBw = sAw + 128*SAP;                      // [128][SAP]
    float*    stage = (float*)(smem + 20480);           // 32x132 fp32 | 128x36 epi

    int bt = blockIdx.z;
    int b = bt / Tc, t = bt % Tc;
    int m0 = blockIdx.y * 128;
    int n0 = blockIdx.x * 128;
    int tid = threadIdx.x, lane = tid & 31, wid = tid >> 5;
    int wm = (wid & 3) * 32;
    int wn = (wid >> 2) * 64;
    int r8 = tid >> 3;            // 0..31
    int c8 = (tid & 7) * 4;

    const float* tb = src + (size_t)b*CTL + (size_t)t*Lc;   // which<2 A source
    const float* Ab = g_o + (size_t)bt*Lc*Cc;               // which==2

    uint32_t adA = smem_u32(sAw) + ((((wm + (lane & 15))*SAP) + ((lane >> 4) << 2)) << 2);
    uint32_t adB = smem_u32(sBw) + ((((wn + (lane & 7) + ((lane >> 4) << 3))*SAP)
                                     + (((lane >> 3) & 1) << 2)) << 2);

    float acc[2][8][4] = {};
    float4 pA[4], pB[4];

    // prefetch k0 = 0
    if (which == 2) {
        #pragma unroll
        for (int i = 0; i < 4; ++i)
            pA[i] = *(const float4*)(Ab + (size_t)(m0 + r8 + i*32)*Cc + c8);
    } else {
        #pragma unroll
        for (int i = 0; i < 4; ++i)
            pA[i] = *(const float4*)(tb + (size_t)r8*TL + m0 + c8 + i*32);
    }
    #pragma unroll
    for (int i = 0; i < 4; ++i)
        pB[i] = *(const float4*)(W + (size_t)(n0 + r8 + i*32)*Cc + c8);

    for (int k0 = 0; k0 < Cc; k0 += 32) {
        __syncthreads();        // prev mma done before smem overwrite
        #pragma unroll
        for (int i = 0; i < 4; ++i) {
            uint2 u = make_uint2(packbf(pB[i].x, pB[i].y), packbf(pB[i].z, pB[i].w));
            *(uint2*)&sBw[(r8 + i*32)*SAP + (c8 >> 1)] = u;
        }
        if (which == 2) {
            #pragma unroll
            for (int i = 0; i < 4; ++i) {
                uint2 u = make_uint2(packbf(pA[i].x, pA[i].y), packbf(pA[i].z, pA[i].w));
                *(uint2*)&sAw[(r8 + i*32)*SAP + (c8 >> 1)] = u;
            }
        } else {
            #pragma unroll
            for (int i = 0; i < 4; ++i)
                *(float4*)&stage[r8*132 + c8 + i*32] = pA[i];
        }
        __syncthreads();
        if (which < 2) {
            int mrow = tid >> 1, kw0 = (tid & 1) * 8;
            #pragma unroll
            for (int i2 = 0; i2 < 8; ++i2) {
                int kw = kw0 + i2;
                sAw[mrow*SAP + kw] =
                    packbf(stage[(2*kw)*132 + mrow], stage[(2*kw+1)*132 + mrow]);
            }
        }
        int kn = k0 + 32;
        if (kn < Cc) {
            if (which == 2) {
                #pragma unroll
                for (int i = 0; i < 4; ++i)
                    pA[i] = *(const float4*)(Ab + (size_t)(m0 + r8 + i*32)*Cc + kn + c8);
            } else {
                #pragma unroll
                for (int i = 0; i < 4; ++i)
                    pA[i] = *(const float4*)(tb + (size_t)(kn + r8)*TL + m0 + c8 + i*32);
            }
            #pragma unroll
            for (int i = 0; i < 4; ++i)
                pB[i] = *(const float4*)(W + (size_t)(n0 + r8 + i*32)*Cc + kn + c8);
        }
        if (which < 2) __syncthreads();
        #pragma unroll
        for (int ks = 0; ks < 2; ++ks) {
            uint32_t A0[4], A1[4];
            ldsm4(A0, adA + ((ks*8) << 2));
            ldsm4(A1, adA + ((16*SAP + ks*8) << 2));
            #pragma unroll
            for (int jp = 0; jp < 4; ++jp) {
                uint32_t bb[4];
                ldsm4(bb, adB + ((jp*16*SAP + ks*8) << 2));
                mma_bf16(acc[0][2*jp],   A0, bb[0], bb[1]);
                mma_bf16(acc[1][2*jp],   A1, bb[0], bb[1]);
                mma_bf16(acc[0][2*jp+1], A0, bb[2], bb[3]);
                mma_bf16(acc[1][2*jp+1], A1, bb[2], bb[3]);
            }
        }
    }

    int row = lane >> 2, col = (lane & 3) * 2;
    if (which < 2) {
        // fused normalization epilogue (head = 64 cols = one warp tile column)
        int g = (n0 + wn) >> 6;
        float bb0[8], bb1[8];
        #pragma unroll
        for (int j = 0; j < 8; ++j) {
            int gn = n0 + wn + j*8 + col;
            bb0[j] = bias[gn]; bb1[j] = bias[gn+1];
        }
        unsigned short* dst; float gmul;
        if (which == 0)      { dst = g_qh + ((size_t)(bt*Hc + g))*Lc*HD; gmul = 0.125f; }
        else if (g < 8)      { dst = g_kh + ((size_t)(bt*Hc + g))*Lc*HD; gmul = 1.0f; }
        else                 { dst = g_vh + ((size_t)(bt*Hc + g - 8))*Lc*HD;
                               gmul = g_gw[bt*Hc + g - 8]; }
        #pragma unroll
        for (int i = 0; i < 2; ++i) {
            float ss0 = 0.f, ss1 = 0.f;
            #pragma unroll
            for (int j = 0; j < 8; ++j) {
                float v0 = acc[i][j][0] + bb0[j], v1 = acc[i][j][1] + bb1[j];
                float v2 = acc[i][j][2] + bb0[j], v3 = acc[i][j][3] + bb1[j];
                ss0 += v0*v0 + v1*v1;
                ss1 += v2*v2 + v3*v3;
            }
            ss0 += __shfl_xor_sync(0xffffffffu, ss0, 1);
            ss0 += __shfl_xor_sync(0xffffffffu, ss0, 2);
            ss1 += __shfl_xor_sync(0xffffffffu, ss1, 1);
            ss1 += __shfl_xor_sync(0xffffffffu, ss1, 2);
            float inv0 = gmul / fmaxf(sqrtf(ss0), 1e-12f);
            float inv1 = gmul / fmaxf(sqrtf(ss1), 1e-12f);
            int l = m0 + wm + i*16 + row;
            uint32_t* p0 = (uint32_t*)(dst + (size_t)l*HD);
            uint32_t* p1 = (uint32_t*)(dst + (size_t)(l+8)*HD);
            #pragma unroll
            for (int j = 0; j < 8; ++j) {
                int dw = j*4 + (lane & 3);
                p0[dw] = packbf((acc[i][j][0]+bb0[j])*inv0, (acc[i][j][1]+bb1[j])*inv0);
                p1[dw] = packbf((acc[i][j][2]+bb0[j])*inv1, (acc[i][j][3]+bb1[j])*inv1);
            }
        }
    } else {
        // fused residual + transpose epilogue: out[b][n][t][m] = acc+bias+ x
        for (int p = 0; p < 4; ++p) {
            __syncthreads();
            if ((wid & 3) == p) {
                #pragma unroll
                for (int i = 0; i < 2; ++i) {
                    #pragma unroll
                    for (int j = 0; j < 8; ++j) {
                        int n  = wn + j*8 + col;
                        int ml = i*16 + row;
                        float b0 = bias[n0+n], b1 = bias[n0+n+1];
                        stage[n*36 + ml]         = acc[i][j][0] + b0;
                        stage[(n+1)*36 + ml]     = acc[i][j][1] + b1;
                        stage[n*36 + ml + 8]     = acc[i][j][2] + b0;
                        stage[(n+1)*36 + ml + 8] = acc[i][j][3] + b1;
                    }
                }
            }
            __syncthreads();
            #pragma unroll
            for (int i = 0; i < 4; ++i) {
                int n  = r8 + i*32;
                int mm = (tid & 7) * 4;
                size_t gidx = (size_t)b*CTL + (size_t)(n0+n)*TL
                            + (size_t)t*Lc + m0 + p*32 + mm;
                float4 xv = *(const float4*)(src + gidx);
                float4 pv = *(float4*)&stage[n*36 + mm];
                *(float4*)&outp[gidx] =
                    make_float4(pv.x+xv.x, pv.y+xv.y, pv.z+xv.z, pv.w+xv.w);
            }
        }
    }
}

// ---------------- flash attention: bf16 mma + ldmatrix ----------------------
__global__ void __launch_bounds__(256) k_attn() {
    __shared__ __align__(16) unsigned short sq[128*72];
    __shared__ __align__(16) unsigned short sk[64*72];
    __shared__ __align__(16) uint32_t svT[64*36];   // segment-swizzled
    int l0 = blockIdx.x * 128;
    int h  = blockIdx.y;
    int bt = blockIdx.z;
    int tid = threadIdx.x, lane = tid & 31, w = tid >> 5;
    const unsigned short* qp = g_qh + ((size_t)(bt*Hc+h)*Lc + l0)*HD;
    const unsigned short* kp = g_kh + ((size_t)(bt*Hc+h)*Lc)*HD;
    const unsigned short* vp = g_vh + ((size_t)(bt*Hc+h)*Lc)*HD;

    for (int i = tid; i < 1024; i += 256) {
        int r = i >> 3, d0 = (i & 7) * 8;
        *(uint4*)&sq[r*72 + d0] = *(const uint4*)(qp + (size_t)r*HD + d0);
    }

    uint32_t aQ = smem_u32(sq) + ((((w*16 + (lane & 15))*36) + ((lane >> 4) << 2)) << 2);
    uint32_t aK = smem_u32(sk) + ((((lane & 7) + ((lane >> 4) << 3))*36
                                   + (((lane >> 3) & 1) << 2)) << 2);
    uint32_t svb = smem_u32(svT);
    int rVbase = (lane & 7) + ((lane >> 4) << 3);
    int csHalf = (lane >> 3) & 1;

    float m0 = -1e30f, m1 = -1e30f, ls0 = 0.f, ls1 = 0.f;
    float o[8][4] = {};
    __syncthreads();

    for (int jt = 0; jt < Lc; jt += 64) {
        for (int i = tid; i < 512; i += 256) {
            int r = i >> 3, d0 = (i & 7) * 8;
            *(uint4*)&sk[r*72 + d0] = *(const uint4*)(kp + (size_t)(jt+r)*HD + d0);
        }
        {
            int kvp = tid >> 3, d0 = (tid & 7) * 8;
            uint4 u0 = *(const uint4*)(vp + (size_t)(jt + 2*kvp)*HD + d0);
            uint4 u1 = *(const uint4*)(vp + (size_t)(jt + 2*kvp + 1)*HD + d0);
            const unsigned short* a = (const unsigned short*)&u0;
            const unsigned short* b = (const unsigned short*)&u1;
            int colw = ((((kvp >> 2) ^ (tid & 7)) << 2) | (kvp & 3));
            #pragma unroll
            for (int j = 0; j < 8; ++j)
                svT[(d0+j)*36 + colw] = (uint32_t)a[j] | ((uint32_t)b[j] << 16);
        }
        __syncthreads();

        // S = Q K^T
        float s[8][4] = {};
        #pragma unroll
        for (int ks = 0; ks < 4; ++ks) {
            uint32_t A[4];
            ldsm4(A, aQ + ((ks*8) << 2));
            #pragma unroll
            for (int jp = 0; jp < 4; ++jp) {
                uint32_t bb[4];
                ldsm4(bb, aK + ((jp*16*36 + ks*8) << 2));
                mma_bf16(s[2*jp],   A, bb[0], bb[1]);
                mma_bf16(s[2*jp+1], A, bb[2], bb[3]);
            }
        }

        // online softmax
        float mx0 = m0, mx1 = m1;
        #pragma unroll
        for (int n = 0; n < 8; ++n) {
            mx0 = fmaxf(mx0, fmaxf(s[n][0], s[n][1]));
            mx1 = fmaxf(mx1, fmaxf(s[n][2], s[n][3]));
        }
        #pragma unroll
        for (int off = 1; off <= 2; off <<= 1) {
            mx0 = fmaxf(mx0, __shfl_xor_sync(0xffffffffu, mx0, off));
            mx1 = fmaxf(mx1, __shfl_xor_sync(0xffffffffu, mx1, off));
        }
        float al0 = __expf(m0 - mx0), al1 = __expf(m1 - mx1);
        float rs0 = 0.f, rs1 = 0.f;
        #pragma unroll
        for (int n = 0; n < 8; ++n) {
            s[n][0] = __expf(s[n][0] - mx0);
            s[n][1] = __expf(s[n][1] - mx0);
            s[n][2] = __expf(s[n][2] - mx1);
            s[n][3] = __expf(s[n][3] - mx1);
            rs0 += s[n][0] + s[n][1];
            rs1 += s[n][2] + s[n][3];
        }
        #pragma unroll
        for (int off = 1; off <= 2; off <<= 1) {
            rs0 += __shfl_xor_sync(0xffffffffu, rs0, off);
            rs1 += __shfl_xor_sync(0xffffffffu, rs1, off);
        }
        ls0 = ls0*al0 + rs0;
        ls1 = ls1*al1 + rs1;
        m0 = mx0; m1 = mx1;
        #pragma unroll
        for (int j = 0; j < 8; ++j) {
            o[j][0] *= al0; o[j][1] *= al0; o[j][2] *= al1; o[j][3] *= al1;
        }

        // O += P V
        #pragma unroll
        for (int kv = 0; kv < 4; ++kv) {
            uint32_t A[4];
            A[0] = packbf(s[2*kv][0],   s[2*kv][1]);
            A[1] = packbf(s[2*kv][2],   s[2*kv][3]);
            A[2] = packbf(s[2*kv+1][0], s[2*kv+1][1]);
            A[3] = packbf(s[2*kv+1][2], s[2*kv+1][3]);
            #pragma unroll
            for (int dp = 0; dp < 4; ++dp) {
                int r = dp*16 + rVbase;
                int cs = kv*2 + csHalf;
                uint32_t bb[4];
                ldsm4(bb, svb + ((r*36 + ((cs ^ (r >> 3)) << 2)) << 2));
                mma_bf16(o[2*dp],   A, bb[0], bb[1]);
                mma_bf16(o[2*dp+1], A, bb[2], bb[3]);
            }
        }
        __syncthreads();
    }

    float gwv = g_gw[bt*Hc + h];
    float i0 = gwv / ls0, i1 = gwv / ls1;
    int qr = w*16 + (lane >> 2);
    int grow = bt*Lc + l0 + qr;
    int gcol = h*HD + (lane & 3)*2;
    #pragma unroll
    for (int d = 0; d < 8; ++d) {
        *(float2*)&g_o[(size_t)grow*Cc + gcol + d*8] =
            make_float2(o[d][0]*i0, o[d][1]*i0);
        *(float2*)&g_o[(size_t)(grow+8)*Cc + gcol + d*8] =
            make_float2(o[d][2]*i1, o[d][3]*i1);
    }
}

// ---------------- launcher --------------------------------------------------
extern "C" void kernel_launch(void* const* d_in, const int* in_sizes, int n_in,
                              void* d_out, int out_size) {
    const float* e   = (const float*)d_in[0];
    const float* x   = (const float*)d_in[1];
    const float* Wq  = (const float*)d_in[2];
    const float* bq  = (const float*)d_in[3];
    const float* Wkv = (const float*)d_in[4];
    const float* bkv = (const float*)d_in[5];
    const float* Wm  = (const float*)d_in[6];
    const float* bm  = (const float*)d_in[7];
    const float* Wg1 = (const float*)d_in[8];
    const float* bg1 = (const float*)d_in[9];
    const float* Wg2 = (const float*)d_in[10];
    const float* bg2 = (const float*)d_in[11];
    float* out = (float*)d_out;

    k_pool<<< (BT*Cc*32 + 255)/256, 256 >>>(e);
    k_gate1<<<dim3(4, BT), 256>>>(Wg1, bg1);
    k_gate2<<<BT, 256>>>(Wg2, bg2);
    k_gemm_bf16<<<dim3(4, 4, BT), 256>>>(0, Wq,  bq,  e, nullptr);   // Q + q-norm
    k_gemm_bf16<<<dim3(8, 4, BT), 256>>>(1, Wkv, bkv, x, nullptr);   // KV + k/v-norm
    k_attn<<<dim3(Lc/128, Hc, BT), 256>>>();
    k_gemm_bf16<<<dim3(4, 4, BT), 256>>>(2, Wm, bm, x, out);         // proj + resid
}

// round 6
// speedup vs baseline: 6.2979x; 1.0427x over previous
#include <cuda_runtime.h>
#include <cuda_bf16.h>
#include <math.h>
#include <stdint.h>

#define Bc 4
#define Cc 512
#define Tc 8
#define Lc 512
#define Hc 8
#define HD 64
#define BT 32               // B*T
#define CTL (Cc*Tc*Lc)
#define TL  (Tc*Lc)
#define SAP 20              // GEMM smem word pitch for row-major bf16x2 tiles
#define XP  68              // K-major A tile word pitch (conflict-free trans-LDSM)

// ---------------- scratch (device globals; no allocation allowed) ----------
__device__ __align__(16) float g_pooled[BT*Cc];
__device__ __align__(16) float g_h1   [BT*Cc];
__device__ __align__(16) float g_gw   [BT*Hc];
__device__ __align__(16) unsigned short g_qh[(size_t)BT*Hc*Lc*HD];  // bf16, 0.125 folded
__device__ __align__(16) unsigned short g_kh[(size_t)BT*Hc*Lc*HD];  // bf16
__device__ __align__(16) unsigned short g_vh[(size_t)BT*Hc*Lc*HD];  // bf16, gw folded
__device__ __align__(16) unsigned short g_oh[(size_t)BT*Lc*Cc];     // bf16 attn out

// ---------------- helpers ---------------------------------------------------
__device__ __forceinline__ void mma_bf16(float c[4], const uint32_t a[4],
                                         uint32_t b0, uint32_t b1) {
    asm volatile(
        "mma.sync.aligned.m16n8k16.row.col.f32.bf16.bf16.f32 "
        "{%0,%1,%2,%3},{%4,%5,%6,%7},{%8,%9},{%0,%1,%2,%3};"
        : "+f"(c[0]), "+f"(c[1]), "+f"(c[2]), "+f"(c[3])
        : "r"(a[0]), "r"(a[1]), "r"(a[2]), "r"(a[3]), "r"(b0), "r"(b1));
}
__device__ __forceinline__ uint32_t packbf(float lo, float hi) {
    uint32_t r;
    asm("cvt.rn.bf16x2.f32 %0, %1, %2;" : "=r"(r) : "f"(hi), "f"(lo));
    return r;
}
__device__ __forceinline__ void ldsm4(uint32_t a[4], uint32_t addr) {
    asm volatile("ldmatrix.sync.aligned.m8n8.x4.shared.b16 {%0,%1,%2,%3}, [%4];"
        : "=r"(a[0]), "=r"(a[1]), "=r"(a[2]), "=r"(a[3]) : "r"(addr));
}
__device__ __forceinline__ void ldsm4t(uint32_t a[4], uint32_t addr) {
    asm volatile("ldmatrix.sync.aligned.m8n8.x4.trans.shared.b16 {%0,%1,%2,%3}, [%4];"
        : "=r"(a[0]), "=r"(a[1]), "=r"(a[2]), "=r"(a[3]) : "r"(addr));
}
__device__ __forceinline__ uint32_t smem_u32(const void* p) {
    return (uint32_t)__cvta_generic_to_shared(p);
}

// ---------------- pooled[bt,c] = mean_l e[b,c,t,l] --------------------------
__global__ void k_pool(const float* __restrict__ e) {
    int w    = (blockIdx.x * blockDim.x + threadIdx.x) >> 5;
    int lane = threadIdx.x & 31;
    if (w >= BT*Cc) return;
    int bt = w / Cc, c = w % Cc;
    int b = bt / Tc, t = bt % Tc;
    const float* p = e + (size_t)b*CTL + (size_t)c*TL + (size_t)t*Lc;
    float s = 0.f;
    #pragma unroll 4
    for (int l = lane; l < Lc; l += 32) s += p[l];
    #pragma unroll
    for (int o = 16; o; o >>= 1) s += __shfl_xor_sync(0xffffffffu, s, o);
    if (!lane) g_pooled[w] = s * (1.0f/Lc);
}

// ---------------- gate layer 1 ---------------------------------------------
__global__ void __launch_bounds__(256) k_gate1(
        const float* __restrict__ Wg1, const float* __restrict__ bg1) {
    __shared__ float sp[Cc];
    int bt = blockIdx.y;
    int r0 = blockIdx.x * 128;
    int tid = threadIdx.x, warp = tid >> 5, lane = tid & 31;
    sp[tid] = g_pooled[bt*Cc + tid];
    sp[tid+256] = g_pooled[bt*Cc + tid + 256];
    __syncthreads();
    const float4* pp = (const float4*)sp;
    #pragma unroll
    for (int i = 0; i < 16; ++i) {
        int r = r0 + warp*16 + i;
        const float4* wr = (const float4*)(Wg1 + (size_t)r*Cc);
        float a = 0.f;
        #pragma unroll
        for (int k = lane; k < Cc/4; k += 32) {
            float4 wv = wr[k]; float4 pv = pp[k];
            a += wv.x*pv.x + wv.y*pv.y + wv.z*pv.z + wv.w*pv.w;
        }
        #pragma unroll
        for (int o = 16; o; o >>= 1) a += __shfl_xor_sync(0xffffffffu, a, o);
        if (!lane) g_h1[bt*Cc + r] = tanhf(a + bg1[r]);
    }
}

// ---------------- gate layer 2 + softmax ------------------------------------
__global__ void __launch_bounds__(256) k_gate2(
        const float* __restrict__ Wg2, const float* __restrict__ bg2) {
    __shared__ float sg[Hc];
    int bt = blockIdx.x;
    int tid = threadIdx.x, warp = tid >> 5, lane = tid & 31;
    if (warp < Hc) {
        const float4* w2 = (const float4*)(Wg2 + (size_t)warp*Cc);
        const float4* hp = (const float4*)(g_h1 + bt*Cc);
        float a = 0.f;
        #pragma unroll
        for (int k = lane; k < Cc/4; k += 32) {
            float4 wv = w2[k]; float4 hv = hp[k];
            a += wv.x*hv.x + wv.y*hv.y + wv.z*hv.z + wv.w*hv.w;
        }
        #pragma unroll
        for (int o = 16; o; o >>= 1) a += __shfl_xor_sync(0xffffffffu, a, o);
        if (!lane) sg[warp] = a + bg2[warp];
    }
    __syncthreads();
    if (tid == 0) {
        float mx = sg[0];
        #pragma unroll
        for (int h = 1; h < Hc; ++h) mx = fmaxf(mx, sg[h]);
        float ex[Hc], ssum = 0.f;
        #pragma unroll
        for (int h = 0; h < Hc; ++h) { ex[h] = expf(sg[h]-mx); ssum += ex[h]; }
        #pragma unroll
        for (int h = 0; h < Hc; ++h) g_gw[bt*Hc+h] = ex[h]/ssum;
    }
}

// ---------------- bf16 tensor-core GEMM -------------------------------------
// which 0: A = e slab (K-major, ldsm.trans), fused q-norm -> g_qh
// which 1: A = x slab (K-major, ldsm.trans), fused k/v-norm -> g_kh/g_vh
// which 2: A = g_oh (bf16 row-major),       fused residual+transpose -> out
__global__ void __launch_bounds__(256, 2) k_gemm_bf16(int which,
        const float* __restrict__ W, const float* __restrict__ bias,
        const float* __restrict__ src, float* __restrict__ outp) {
    __shared__ __align__(16) unsigned char smem[38912];
    uint32_t* sBw = (uint32_t*)smem;                    // [128][SAP]
    uint32_t* sAw = sBw + 128*SAP;                      // [128][SAP] (which==2)
    uint32_t* sXw = sAw;                                // [32][XP]   (which<2)
    float*    stage = (float*)(smem + 20480);           // 128x36 epilogue fp32

    int bt = blockIdx.z;
    int b = bt / Tc, t = bt % Tc;
    int m0 = blockIdx.y * 128;
    int n0 = blockIdx.x * 128;
    int tid = threadIdx.x, lane = tid & 31, wid = tid >> 5;
    int wm = (wid & 3) * 32;
    int wn = (wid >> 2) * 64;
    int r8 = tid >> 3;            // 0..31
    int c8 = (tid & 7) * 4;

    const float* tb = src + (size_t)b*CTL + (size_t)t*Lc;       // which<2
    const uint32_t* Ao = (const uint32_t*)g_oh + (size_t)bt*Lc*(Cc/2); // which==2

    // LDSM addresses
    uint32_t adB = smem_u32(sBw) + ((((wn + (lane & 7) + ((lane >> 4) << 3))*SAP)
                                     + (((lane >> 3) & 1) << 2)) << 2);
    uint32_t adA = smem_u32(sAw) + ((((wm + (lane & 15))*SAP) + ((lane >> 4) << 2)) << 2);
    // trans-LDSM (which<2): row = k, col = m-words
    uint32_t adX = smem_u32(sXw)
        + ((((lane & 7) + ((lane >> 4) << 3))*XP + (wm >> 1) + (((lane >> 3) & 1) << 2)) << 2);

    float acc[2][8][4] = {};
    float4 pB[4], pA[4];
    uint4  qA[2];

    // prefetch k0 = 0
    #pragma unroll
    for (int i = 0; i < 4; ++i)
        pB[i] = *(const float4*)(W + (size_t)(n0 + r8 + i*32)*Cc + c8);
    if (which == 2) {
        const uint32_t* ap = Ao + (size_t)(tid >> 1)*(Cc/2) + (tid & 1)*8;
        qA[0] = *(const uint4*)(ap);
        qA[1] = *(const uint4*)(ap + 4);
    } else {
        #pragma unroll
        for (int i = 0; i < 4; ++i)
            pA[i] = *(const float4*)(tb + (size_t)r8*TL + m0 + (tid & 7)*16 + 4*i);
    }

    for (int k0 = 0; k0 < Cc; k0 += 32) {
        __syncthreads();
        #pragma unroll
        for (int i = 0; i < 4; ++i) {
            uint2 u = make_uint2(packbf(pB[i].x, pB[i].y), packbf(pB[i].z, pB[i].w));
            *(uint2*)&sBw[(r8 + i*32)*SAP + (c8 >> 1)] = u;
        }
        if (which == 2) {
            uint32_t* dp = &sAw[(tid >> 1)*SAP + (tid & 1)*8];
            *(uint4*)dp       = qA[0];
            *(uint4*)(dp + 4) = qA[1];
        } else {
            // K-major store: sX[k=r8][m-words], no transpose needed
            uint32_t* dp = &sXw[r8*XP + (tid & 7)*8];
            #pragma unroll
            for (int i = 0; i < 4; ++i) {
                *(uint2*)(dp + 2*i) =
                    make_uint2(packbf(pA[i].x, pA[i].y), packbf(pA[i].z, pA[i].w));
            }
        }
        int kn = k0 + 32;
        if (kn < Cc) {
            #pragma unroll
            for (int i = 0; i < 4; ++i)
                pB[i] = *(const float4*)(W + (size_t)(n0 + r8 + i*32)*Cc + kn + c8);
            if (which == 2) {
                const uint32_t* ap = Ao + (size_t)(tid >> 1)*(Cc/2) + (kn >> 1) + (tid & 1)*8;
                qA[0] = *(const uint4*)(ap);
                qA[1] = *(const uint4*)(ap + 4);
            } else {
                #pragma unroll
                for (int i = 0; i < 4; ++i)
                    pA[i] = *(const float4*)(tb + (size_t)(kn + r8)*TL + m0 + (tid & 7)*16 + 4*i);
            }
        }
        __syncthreads();
        #pragma unroll
        for (int ks = 0; ks < 2; ++ks) {
            uint32_t A0[4], A1[4];
            if (which == 2) {
                ldsm4(A0, adA + ((ks*8) << 2));
                ldsm4(A1, adA + ((16*SAP + ks*8) << 2));
            } else {
                ldsm4t(A0, adX + ((ks*16*XP) << 2));
                ldsm4t(A1, adX + ((ks*16*XP + 8) << 2));
            }
            #pragma unroll
            for (int jp = 0; jp < 4; ++jp) {
                uint32_t bb[4];
                ldsm4(bb, adB + ((jp*16*SAP + ks*8) << 2));
                mma_bf16(acc[0][2*jp],   A0, bb[0], bb[1]);
                mma_bf16(acc[1][2*jp],   A1, bb[0], bb[1]);
                mma_bf16(acc[0][2*jp+1], A0, bb[2], bb[3]);
                mma_bf16(acc[1][2*jp+1], A1, bb[2], bb[3]);
            }
        }
    }

    int row = lane >> 2, col = (lane & 3) * 2;
    if (which < 2) {
        // fused normalization epilogue (head = 64 cols = one warp tile column)
        int g = (n0 + wn) >> 6;
        float bb0[8], bb1[8];
        #pragma unroll
        for (int j = 0; j < 8; ++j) {
            int gn = n0 + wn + j*8 + col;
            bb0[j] = bias[gn]; bb1[j] = bias[gn+1];
        }
        unsigned short* dst; float gmul;
        if (which == 0)      { dst = g_qh + ((size_t)(bt*Hc + g))*Lc*HD; gmul = 0.125f; }
        else if (g < 8)      { dst = g_kh + ((size_t)(bt*Hc + g))*Lc*HD; gmul = 1.0f; }
        else                 { dst = g_vh + ((size_t)(bt*Hc + g - 8))*Lc*HD;
                               gmul = g_gw[bt*Hc + g - 8]; }
        #pragma unroll
        for (int i = 0; i < 2; ++i) {
            float ss0 = 0.f, ss1 = 0.f;
            #pragma unroll
            for (int j = 0; j < 8; ++j) {
                float v0 = acc[i][j][0] + bb0[j], v1 = acc[i][j][1] + bb1[j];
                float v2 = acc[i][j][2] + bb0[j], v3 = acc[i][j][3] + bb1[j];
                ss0 += v0*v0 + v1*v1;
                ss1 += v2*v2 + v3*v3;
            }
            ss0 += __shfl_xor_sync(0xffffffffu, ss0, 1);
            ss0 += __shfl_xor_sync(0xffffffffu, ss0, 2);
            ss1 += __shfl_xor_sync(0xffffffffu, ss1, 1);
            ss1 += __shfl_xor_sync(0xffffffffu, ss1, 2);
            float inv0 = gmul / fmaxf(sqrtf(ss0), 1e-12f);
            float inv1 = gmul / fmaxf(sqrtf(ss1), 1e-12f);
            int l = m0 + wm + i*16 + row;
            uint32_t* p0 = (uint32_t*)(dst + (size_t)l*HD);
            uint32_t* p1 = (uint32_t*)(dst + (size_t)(l+8)*HD);
            #pragma unroll
            for (int j = 0; j < 8; ++j) {
                int dw = j*4 + (lane & 3);
                p0[dw] = packbf((acc[i][j][0]+bb0[j])*inv0, (acc[i][j][1]+bb1[j])*inv0);
                p1[dw] = packbf((acc[i][j][2]+bb0[j])*inv1, (acc[i][j][3]+bb1[j])*inv1);
            }
        }
    } else {
        // fused residual + transpose epilogue: out[b][n][t][m] = acc+bias+x
        for (int p = 0; p < 4; ++p) {
            __syncthreads();
            if ((wid & 3) == p) {
                #pragma unroll
                for (int i = 0; i < 2; ++i) {
                    #pragma unroll
                    for (int j = 0; j < 8; ++j) {
                        int n  = wn + j*8 + col;
                        int ml = i*16 + row;
                        float b0 = bias[n0+n], b1 = bias[n0+n+1];
                        stage[n*36 + ml]         = acc[i][j][0] + b0;
                        stage[(n+1)*36 + ml]     = acc[i][j][1] + b1;
                        stage[n*36 + ml + 8]     = acc[i][j][2] + b0;
                        stage[(n+1)*36 + ml + 8] = acc[i][j][3] + b1;
                    }
                }
            }
            __syncthreads();
            #pragma unroll
            for (int i = 0; i < 4; ++i) {
                int n  = r8 + i*32;
                int mm = (tid & 7) * 4;
                size_t gidx = (size_t)b*CTL + (size_t)(n0+n)*TL
                            + (size_t)t*Lc + m0 + p*32 + mm;
                float4 xv = *(const float4*)(src + gidx);
                float4 pv = *(float4*)&stage[n*36 + mm];
                *(float4*)&outp[gidx] =
                    make_float4(pv.x+xv.x, pv.y+xv.y, pv.z+xv.z, pv.w+xv.w);
            }
        }
    }
}

// ---------------- flash attention: bf16 mma + ldmatrix ----------------------
__global__ void __launch_bounds__(256) k_attn() {
    __shared__ __align__(16) unsigned short sq[128*72];
    __shared__ __align__(16) unsigned short sk[64*72];
    __shared__ __align__(16) uint32_t svT[64*36];   // segment-swizzled
    int l0 = blockIdx.x * 128;
    int h  = blockIdx.y;
    int bt = blockIdx.z;
    int tid = threadIdx.x, lane = tid & 31, w = tid >> 5;
    const unsigned short* qp = g_qh + ((size_t)(bt*Hc+h)*Lc + l0)*HD;
    const unsigned short* kp = g_kh + ((size_t)(bt*Hc+h)*Lc)*HD;
    const unsigned short* vp = g_vh + ((size_t)(bt*Hc+h)*Lc)*HD;

    for (int i = tid; i < 1024; i += 256) {
        int r = i >> 3, d0 = (i & 7) * 8;
        *(uint4*)&sq[r*72 + d0] = *(const uint4*)(qp + (size_t)r*HD + d0);
    }

    uint32_t aQ = smem_u32(sq) + ((((w*16 + (lane & 15))*36) + ((lane >> 4) << 2)) << 2);
    uint32_t aK = smem_u32(sk) + ((((lane & 7) + ((lane >> 4) << 3))*36
                                   + (((lane >> 3) & 1) << 2)) << 2);
    uint32_t svb = smem_u32(svT);
    int rVbase = (lane & 7) + ((lane >> 4) << 3);
    int csHalf = (lane >> 3) & 1;

    float m0 = -1e30f, m1 = -1e30f, ls0 = 0.f, ls1 = 0.f;
    float o[8][4] = {};
    __syncthreads();

    for (int jt = 0; jt < Lc; jt += 64) {
        for (int i = tid; i < 512; i += 256) {
            int r = i >> 3, d0 = (i & 7) * 8;
            *(uint4*)&sk[r*72 + d0] = *(const uint4*)(kp + (size_t)(jt+r)*HD + d0);
        }
        {
            int kvp = tid >> 3, d0 = (tid & 7) * 8;
            uint4 u0 = *(const uint4*)(vp + (size_t)(jt + 2*kvp)*HD + d0);
            uint4 u1 = *(const uint4*)(vp + (size_t)(jt + 2*kvp + 1)*HD + d0);
            const unsigned short* a = (const unsigned short*)&u0;
            const unsigned short* b = (const unsigned short*)&u1;
            int colw = ((((kvp >> 2) ^ (tid & 7)) << 2) | (kvp & 3));
            #pragma unroll
            for (int j = 0; j < 8; ++j)
                svT[(d0+j)*36 + colw] = (uint32_t)a[j] | ((uint32_t)b[j] << 16);
        }
        __syncthreads();

        // S = Q K^T
        float s[8][4] = {};
        #pragma unroll
        for (int ks = 0; ks < 4; ++ks) {
            uint32_t A[4];
            ldsm4(A, aQ + ((ks*8) << 2));
            #pragma unroll
            for (int jp = 0; jp < 4; ++jp) {
                uint32_t bb[4];
                ldsm4(bb, aK + ((jp*16*36 + ks*8) << 2));
                mma_bf16(s[2*jp],   A, bb[0], bb[1]);
                mma_bf16(s[2*jp+1], A, bb[2], bb[3]);
            }
        }

        // online softmax
        float mx0 = m0, mx1 = m1;
        #pragma unroll
        for (int n = 0; n < 8; ++n) {
            mx0 = fmaxf(mx0, fmaxf(s[n][0], s[n][1]));
            mx1 = fmaxf(mx1, fmaxf(s[n][2], s[n][3]));
        }
        #pragma unroll
        for (int off = 1; off <= 2; off <<= 1) {
            mx0 = fmaxf(mx0, __shfl_xor_sync(0xffffffffu, mx0, off));
            mx1 = fmaxf(mx1, __shfl_xor_sync(0xffffffffu, mx1, off));
        }
        float al0 = __expf(m0 - mx0), al1 = __expf(m1 - mx1);
        float rs0 = 0.f, rs1 = 0.f;
        #pragma unroll
        for (int n = 0; n < 8; ++n) {
            s[n][0] = __expf(s[n][0] - mx0);
            s[n][1] = __expf(s[n][1] - mx0);
            s[n][2] = __expf(s[n][2] - mx1);
            s[n][3] = __expf(s[n][3] - mx1);
            rs0 += s[n][0] + s[n][1];
            rs1 += s[n][2] + s[n][3];
        }
        #pragma unroll
        for (int off = 1; off <= 2; off <<= 1) {
            rs0 += __shfl_xor_sync(0xffffffffu, rs0, off);
            rs1 += __shfl_xor_sync(0xffffffffu, rs1, off);
        }
        ls0 = ls0*al0 + rs0;
        ls1 = ls1*al1 + rs1;
        m0 = mx0; m1 = mx1;
        #pragma unroll
        for (int j = 0; j < 8; ++j) {
            o[j][0] *= al0; o[j][1] *= al0; o[j][2] *= al1; o[j][3] *= al1;
        }

        // O += P V
        #pragma unroll
        for (int kv = 0; kv < 4; ++kv) {
            uint32_t A[4];
            A[0] = packbf(s[2*kv][0],   s[2*kv][1]);
            A[1] = packbf(s[2*kv][2],   s[2*kv][3]);
            A[2] = packbf(s[2*kv+1][0], s[2*kv+1][1]);
            A[3] = packbf(s[2*kv+1][2], s[2*kv+1][3]);
            #pragma unroll
            for (int dp = 0; dp < 4; ++dp) {
                int r = dp*16 + rVbase;
                int cs = kv*2 + csHalf;
                uint32_t bb[4];
                ldsm4(bb, svb + ((r*36 + ((cs ^ (r >> 3)) << 2)) << 2));
                mma_bf16(o[2*dp],   A, bb[0], bb[1]);
                mma_bf16(o[2*dp+1], A, bb[2], bb[3]);
            }
        }
        __syncthreads();
    }

    // epilogue -> bf16 g_oh
    float gwv = g_gw[bt*Hc + h];
    float i0 = gwv / ls0, i1 = gwv / ls1;
    int qr = w*16 + (lane >> 2);
    int grow = bt*Lc + l0 + qr;
    uint32_t* ow = (uint32_t*)g_oh;
    int base0 = grow*(Cc/2) + h*(HD/2) + (lane & 3);
    int base1 = (grow+8)*(Cc/2) + h*(HD/2) + (lane & 3);
    #pragma unroll
    for (int d = 0; d < 8; ++d) {
        ow[base0 + d*4] = packbf(o[d][0]*i0, o[d][1]*i0);
        ow[base1 + d*4] = packbf(o[d][2]*i1, o[d][3]*i1);
    }
}

// ---------------- launcher --------------------------------------------------
extern "C" void kernel_launch(void* const* d_in, const int* in_sizes, int n_in,
                              void* d_out, int out_size) {
    const float* e   = (const float*)d_in[0];
    const float* x   = (const float*)d_in[1];
    const float* Wq  = (const float*)d_in[2];
    const float* bq  = (const float*)d_in[3];
    const float* Wkv = (const float*)d_in[4];
    const float* bkv = (const float*)d_in[5];
    const float* Wm  = (const float*)d_in[6];
    const float* bm  = (const float*)d_in[7];
    const float* Wg1 = (const float*)d_in[8];
    const float* bg1 = (const float*)d_in[9];
    const float* Wg2 = (const float*)d_in[10];
    const float* bg2 = (const float*)d_in[11];
    float* out = (float*)d_out;

    k_pool<<< (BT*Cc*32 + 255)/256, 256 >>>(e);
    k_gate1<<<dim3(4, BT), 256>>>(Wg1, bg1);
    k_gate2<<<BT, 256>>>(Wg2, bg2);
    k_gemm_bf16<<<dim3(4, 4, BT), 256>>>(0, Wq,  bq,  e, nullptr);   // Q + q-norm
    k_gemm_bf16<<<dim3(8, 4, BT), 256>>>(1, Wkv, bkv, x, nullptr);   // KV + k/v-norm
    k_attn<<<dim3(Lc/128, Hc, BT), 256>>>();
    k_gemm_bf16<<<dim3(4, 4, BT), 256>>>(2, Wm, bm, x, out);         // proj + resid
}